// round 14
// baseline (speedup 1.0000x reference)
#include <cuda_runtime.h>
#include <cuda_bf16.h>
#include <cuda_fp16.h>
#include <stdint.h>
typedef __nv_bfloat16 bf;
typedef __half hf;

#define B 8
#define N0 2048
#define N1 1024
#define HD 384
#define NH 6
#define M0 (B*N0)
#define M1 (B*N1)
#define MT (M0+M1)
#define OUT_ELEMS ((size_t)B*N0*768)

__device__ __align__(128) bf g_ih0[M0*768],  g_il0[M0*768];
__device__ __align__(128) bf g_ih1[M1*1536], g_il1[M1*1536];
__device__ __align__(128) hf g_if0[M0*768],  g_if1[M1*1536];
__device__ __align__(128) bf g_wh0[2][768*768],  g_wl0[2][768*768];
__device__ __align__(128) bf g_wh1[2][1536*768], g_wl1[2][1536*768];
__device__ __align__(128) hf g_wv0f[768*768], g_wv1f[1536*768], g_wo[1536*768];
__device__ __align__(128) bf g_qh[MT*HD], g_ql[MT*HD], g_kh[MT*HD], g_kl[MT*HD];
__device__ __align__(128) hf g_v[MT*HD];
__device__ __align__(128) hf g_o[MT*HD];

__device__ __forceinline__ uint32_t sm_u32(const void* p) {
    return (uint32_t)__cvta_generic_to_shared(p);
}
__device__ __forceinline__ void ldsm4(uint32_t r[4], uint32_t a) {
    asm volatile("ldmatrix.sync.aligned.m8n8.x4.shared.b16 {%0,%1,%2,%3}, [%4];"
        : "=r"(r[0]), "=r"(r[1]), "=r"(r[2]), "=r"(r[3]) : "r"(a));
}
__device__ __forceinline__ void ldsm4t(uint32_t r[4], uint32_t a) {
    asm volatile("ldmatrix.sync.aligned.m8n8.x4.trans.shared.b16 {%0,%1,%2,%3}, [%4];"
        : "=r"(r[0]), "=r"(r[1]), "=r"(r[2]), "=r"(r[3]) : "r"(a));
}
__device__ __forceinline__ void mma_bf(float d[4], const uint32_t a[4],
                                       uint32_t b0, uint32_t b1) {
    asm volatile("mma.sync.aligned.m16n8k16.row.col.f32.bf16.bf16.f32 "
        "{%0,%1,%2,%3}, {%4,%5,%6,%7}, {%8,%9}, {%0,%1,%2,%3};"
        : "+f"(d[0]), "+f"(d[1]), "+f"(d[2]), "+f"(d[3])
        : "r"(a[0]), "r"(a[1]), "r"(a[2]), "r"(a[3]), "r"(b0), "r"(b1));
}
__device__ __forceinline__ void mma_hf(float d[4], const uint32_t a[4],
                                       uint32_t b0, uint32_t b1) {
    asm volatile("mma.sync.aligned.m16n8k16.row.col.f32.f16.f16.f32 "
        "{%0,%1,%2,%3}, {%4,%5,%6,%7}, {%8,%9}, {%0,%1,%2,%3};"
        : "+f"(d[0]), "+f"(d[1]), "+f"(d[2]), "+f"(d[3])
        : "r"(a[0]), "r"(a[1]), "r"(a[2]), "r"(a[3]), "r"(b0), "r"(b1));
}
__device__ __forceinline__ uint32_t bpack(float lo, float hi) {
    __nv_bfloat162 t = __floats2bfloat162_rn(lo, hi);
    return *reinterpret_cast<uint32_t*>(&t);
}
__device__ __forceinline__ void fsplit(float x, float& h, float& l) {
    bf b = __float2bfloat16(x);
    h = __bfloat162float(b);
    l = x - h;
}
__device__ __forceinline__ uint32_t hpack(float lo, float hi) {
    __half2 t = __floats2half2_rn(lo, hi);
    return *reinterpret_cast<uint32_t*>(&t);
}
__device__ __forceinline__ void cpa16(uint32_t d, const void* s) {
    asm volatile("cp.async.cg.shared.global [%0], [%1], 16;" :: "r"(d), "l"(s));
}
__device__ __forceinline__ void cp_commit() { asm volatile("cp.async.commit_group;"); }
__device__ __forceinline__ void cp_wait0()  { asm volatile("cp.async.wait_group 0;"); }
__device__ __forceinline__ void cp_wait1()  { asm volatile("cp.async.wait_group 1;"); }

// ---- prep kernels ----
struct SJob  { const float* s; bf* h; bf* l; };
struct SJobs { SJob j[2]; };
__global__ void splitk(SJobs js, int n) {
    SJob J = js.j[blockIdx.z];
    for (int i = (blockIdx.x*256 + threadIdx.x)*4; i < n; i += gridDim.x*256*4) {
        float4 v = *(const float4*)(J.s + i);
        float h0,l0,h1,l1,h2,l2,h3,l3;
        fsplit(v.x,h0,l0); fsplit(v.y,h1,l1); fsplit(v.z,h2,l2); fsplit(v.w,h3,l3);
        *(uint2*)(J.h + i) = make_uint2(bpack(h0,h1), bpack(h2,h3));
        *(uint2*)(J.l + i) = make_uint2(bpack(l0,l1), bpack(l2,l3));
    }
}
struct S3Job  { const float* s; bf* h; bf* l; hf* f; };
struct S3Jobs { S3Job j[2]; };
__global__ void split3(S3Jobs js, int n) {
    S3Job J = js.j[blockIdx.z];
    for (int i = (blockIdx.x*256 + threadIdx.x)*4; i < n; i += gridDim.x*256*4) {
        float4 v = *(const float4*)(J.s + i);
        float h0,l0,h1,l1,h2,l2,h3,l3;
        fsplit(v.x,h0,l0); fsplit(v.y,h1,l1); fsplit(v.z,h2,l2); fsplit(v.w,h3,l3);
        *(uint2*)(J.h + i) = make_uint2(bpack(h0,h1), bpack(h2,h3));
        *(uint2*)(J.l + i) = make_uint2(bpack(l0,l1), bpack(l2,l3));
        *(uint2*)(J.f + i) = make_uint2(hpack(v.x,v.y), hpack(v.z,v.w));
    }
}
struct CJob  { const float* s; hf* d; int n; };
struct CJobs { CJob j[3]; };
__global__ void cvt3(CJobs js) {
    CJob J = js.j[blockIdx.z];
    for (int i = (blockIdx.x*256 + threadIdx.x)*4; i < J.n; i += gridDim.x*256*4) {
        float4 v = *(const float4*)(J.s + i);
        *(uint2*)(J.d + i) = make_uint2(hpack(v.x, v.y), hpack(v.z, v.w));
    }
}

// ---- tile constants ----
#define GAS 40
#define GBS 136

// bf16 3-term ktile
__device__ __forceinline__ void mma_ktile(
    uint32_t aBH, uint32_t aBL, uint32_t bBH, uint32_t bBL,
    int mrow, int ncol, int lane, float acc[4][4][4])
{
#pragma unroll
    for (int kk = 0; kk < 32; kk += 16) {
        uint32_t ah[4][4], al[4][4];
#pragma unroll
        for (int im = 0; im < 4; im++) {
            uint32_t ad = (uint32_t)((mrow + im*16 + (lane & 15)) * GAS +
                                     kk + ((lane >> 4) << 3)) * 2;
            ldsm4(ah[im], aBH + ad);
            ldsm4(al[im], aBL + ad);
        }
#pragma unroll
        for (int nf = 0; nf < 2; nf++) {
            uint32_t bd = (uint32_t)((kk + (lane & 15)) * GBS + ncol +
                                     nf*16 + ((lane >> 4) << 3)) * 2;
            uint32_t bh4[4], bl4[4];
            ldsm4t(bh4, bBH + bd);
            ldsm4t(bl4, bBL + bd);
#pragma unroll
            for (int im = 0; im < 4; im++) {
#pragma unroll
                for (int j = 0; j < 2; j++) {
                    float* d = acc[im][nf*2 + j];
                    mma_bf(d, ah[im], bh4[2*j], bh4[2*j+1]);
                    mma_bf(d, ah[im], bl4[2*j], bl4[2*j+1]);
                    mma_bf(d, al[im], bh4[2*j], bh4[2*j+1]);
                }
            }
        }
    }
}

// ---- merged Q/K projection, 3-stage cp.async: grid (6, 192) ----
// Level interleave: y%3==2 -> level1 (heavy K), else level0.
struct QLv {
    const bf *Ah, *Al, *Wh, *Wl;
    const float *bq, *bk;
    int K, nseq, wOff;
    long orow;
};
#define QST 37888                       // Ah|Al|Bh|Bl per stage
#define QKV_SMEM (3*QST)                // 113664 B -> 2 CTAs = 222 KB/SM

__global__ __launch_bounds__(256, 2) void qkv_gemm(
    QLv L0, QLv L1,
    bf* __restrict__ qh, bf* __restrict__ ql,
    bf* __restrict__ kh, bf* __restrict__ kl,
    const float* __restrict__ mask)
{
    extern __shared__ char dsc[];
    const uint32_t sb = sm_u32(dsc);
    const int tid = threadIdx.x, lane = tid & 31, warp = tid >> 5;
    const int y = blockIdx.y;
    const int lv = (y % 3) == 2;
    const QLv L = lv ? L1 : L0;
    const int myb = lv ? (y / 3) : (y - y / 3);
    const int sel = blockIdx.x / 3, n0 = (blockIdx.x % 3) * 128;
    const int m0 = myb * 128;
    const int K = L.K;
    const int mrow = (warp >> 2) * 64, ncol = (warp & 3) * 32;

    const bf* Wh = L.Wh + (size_t)sel * K * 768 + L.wOff + n0;
    const bf* Wl = L.Wl + (size_t)sel * K * 768 + L.wOff + n0;
    const float* bias = (sel == 0) ? L.bq : L.bk;
    bf* Ch = (sel == 0) ? qh : kh;
    bf* Cl = (sel == 0) ? ql : kl;
    const bf* aH = L.Ah + (size_t)m0 * K;
    const bf* aL = L.Al + (size_t)m0 * K;

    float acc[4][4][4];
#pragma unroll
    for (int i = 0; i < 4; i++)
#pragma unroll
        for (int j = 0; j < 4; j++)
#pragma unroll
            for (int k = 0; k < 4; k++) acc[i][j][k] = 0.f;

    auto issue = [&](int t) {
        uint32_t s = sb + (t % 3) * QST;
        const bf* aHp = aH + t*32;
        const bf* aLp = aL + t*32;
        const bf* wHp = Wh + (size_t)(t*32) * 768;
        const bf* wLp = Wl + (size_t)(t*32) * 768;
        const int arow = tid >> 1, ak = (tid & 1) << 4;
        const size_t ao = (size_t)arow * K + ak;
        const uint32_t ad = (uint32_t)(arow * GAS + ak) * 2;
        cpa16(s + ad, aHp + ao);          cpa16(s + ad + 16, aHp + ao + 8);
        cpa16(s + 10240 + ad, aLp + ao);  cpa16(s + 10240 + ad + 16, aLp + ao + 8);
        const int brow = tid >> 3, bc = (tid & 7) << 4;
        const size_t bo = (size_t)brow * 768 + bc;
        const uint32_t bd = (uint32_t)(brow * GBS + bc) * 2;
        cpa16(s + 20480 + bd, wHp + bo);  cpa16(s + 20480 + bd + 16, wHp + bo + 8);
        cpa16(s + 29184 + bd, wLp + bo);  cpa16(s + 29184 + bd + 16, wLp + bo + 8);
        cp_commit();
    };

    const int nkt = K / 32;
    issue(0); issue(1);
    for (int t = 0; t < nkt; t++) {
        if (t + 1 < nkt) cp_wait1(); else cp_wait0();
        __syncthreads();
        if (t + 2 < nkt) issue(t + 2);
        uint32_t s = sb + (t % 3) * QST;
        mma_ktile(s, s + 10240, s + 20480, s + 29184, mrow, ncol, lane, acc);
        __syncthreads();
    }

#pragma unroll
    for (int im = 0; im < 4; im++) {
        int r0g = m0 + mrow + im*16 + (lane >> 2);
#pragma unroll
        for (int f = 0; f < 4; f++) {
            int gcol = n0 + ncol + f*8 + ((lane & 3) << 1);
            float* d = acc[im][f];
#pragma unroll
            for (int hfi = 0; hfi < 2; hfi++) {
                int rr = r0g + hfi*8;
                float x0 = d[hfi*2]     + bias[gcol];
                float x1 = d[hfi*2 + 1] + bias[gcol + 1];
                if (sel == 0) {
                    const float* mk = mask + (rr / L.nseq) * 64;
                    x0 = x0*0.125f + mk[gcol & 63];
                    x1 = x1*0.125f + mk[(gcol + 1) & 63];
                }
                size_t o = (size_t)(L.orow + rr) * HD + gcol;
                float h0,l0,h1,l1;
                fsplit(x0,h0,l0); fsplit(x1,h1,l1);
                *(uint32_t*)(Ch + o) = bpack(h0,h1);
                *(uint32_t*)(Cl + o) = bpack(l0,l1);
            }
        }
    }
}

// ---- fp16 1-term ktile ----
__device__ __forceinline__ void mma_ktile_h1(
    uint32_t aB, uint32_t bB, int mrow, int ncol, int lane, float acc[4][4][4])
{
#pragma unroll
    for (int kk = 0; kk < 32; kk += 16) {
        uint32_t ah[4][4];
#pragma unroll
        for (int im = 0; im < 4; im++) {
            uint32_t ad = (uint32_t)((mrow + im*16 + (lane & 15)) * GAS +
                                     kk + ((lane >> 4) << 3)) * 2;
            ldsm4(ah[im], aB + ad);
        }
#pragma unroll
        for (int nf = 0; nf < 2; nf++) {
            uint32_t bd = (uint32_t)((kk + (lane & 15)) * GBS + ncol +
                                     nf*16 + ((lane >> 4) << 3)) * 2;
            uint32_t b4[4];
            ldsm4t(b4, bB + bd);
#pragma unroll
            for (int im = 0; im < 4; im++) {
#pragma unroll
                for (int j = 0; j < 2; j++)
                    mma_hf(acc[im][nf*2 + j], ah[im], b4[2*j], b4[2*j+1]);
            }
        }
    }
}

#define VST ((128*GAS + 32*GBS) * 2)
#define V_SMEM (3*VST)

// ---- merged V projection: grid (3, 192), same level interleave ----
struct VLv { const hf *A, *Wv; const float* bv; int K, wOff; long orow; };
__global__ __launch_bounds__(256, 2) void v_gemm(VLv L0, VLv L1, hf* __restrict__ v)
{
    extern __shared__ char dsc[];
    const int tid = threadIdx.x, lane = tid & 31, warp = tid >> 5;
    const int y = blockIdx.y;
    const int lv = (y % 3) == 2;
    const VLv L = lv ? L1 : L0;
    const int myb = lv ? (y / 3) : (y - y / 3);
    const int n0 = blockIdx.x * 128, m0 = myb * 128;
    const int K = L.K;
    const int mrow = (warp >> 2) * 64, ncol = (warp & 3) * 32;
    const uint32_t sb = sm_u32(dsc);

    float acc[4][4][4];
#pragma unroll
    for (int i = 0; i < 4; i++)
#pragma unroll
        for (int j = 0; j < 4; j++)
#pragma unroll
            for (int k = 0; k < 4; k++) acc[i][j][k] = 0.f;

    auto issue = [&](int t) {
        uint32_t s = sb + (t % 3) * VST;
        const hf* a = L.A + (size_t)m0 * K + t*32;
        const hf* w = L.Wv + (size_t)(t*32) * 768 + L.wOff + n0;
        const int arow = tid >> 1, ak = (tid & 1) << 4;
        const size_t ao = (size_t)arow * K + ak;
        const uint32_t ad = (uint32_t)(arow * GAS + ak) * 2;
        cpa16(s + ad, a + ao);  cpa16(s + ad + 16, a + ao + 8);
        const int brow = tid >> 3, bc = (tid & 7) << 4;
        const size_t bo = (size_t)brow * 768 + bc;
        const uint32_t bd = (uint32_t)(brow * GBS + bc) * 2 + 128*GAS*2;
        cpa16(s + bd, w + bo);  cpa16(s + bd + 16, w + bo + 8);
        cp_commit();
    };

    const int nkt = K / 32;
    issue(0); issue(1);
    for (int t = 0; t < nkt; t++) {
        if (t + 1 < nkt) cp_wait1(); else cp_wait0();
        __syncthreads();
        if (t + 2 < nkt) issue(t + 2);
        uint32_t s = sb + (t % 3) * VST;
        mma_ktile_h1(s, s + 128*GAS*2, mrow, ncol, lane, acc);
        __syncthreads();
    }

#pragma unroll
    for (int im = 0; im < 4; im++) {
        int r0g = m0 + mrow + im*16 + (lane >> 2);
#pragma unroll
        for (int f = 0; f < 4; f++) {
            int gcol = n0 + ncol + f*8 + ((lane & 3) << 1);
            float* d = acc[im][f];
#pragma unroll
            for (int hfi = 0; hfi < 2; hfi++) {
                int rr = r0g + hfi*8;
                *(uint32_t*)(v + (size_t)(L.orow + rr)*HD + gcol) =
                    hpack(d[hfi*2] + L.bv[gcol], d[hfi*2 + 1] + L.bv[gcol + 1]);
            }
        }
    }
}

#define OST VST
#define OUT_SMEM (3*OST)

// ---- output projection: grid (6, 128); y swizzled to mix 24/12-ktile CTAs ----
__global__ __launch_bounds__(256, 2) void out_gemm(
    const hf* __restrict__ o, const hf* __restrict__ Wo,
    const float* __restrict__ bo, float* __restrict__ out)
{
    extern __shared__ char dsc[];
    const int tid = threadIdx.x, lane = tid & 31, warp = tid >> 5;
    const int n0 = blockIdx.x * 128;
    // interleave heavy (lower-half, 24 ktiles) and light (upper-half, 12) CTAs
    const int yi = blockIdx.y >> 1;
    const int batch = yi >> 3, off = yi & 7;
    const int m0 = (batch * 16 + ((blockIdx.y & 1) ? 8 + off : off)) * 128;
    const int mrow = (warp >> 2) * 64, ncol = (warp & 3) * 32;

    const bool lower = (m0 & 2047) < 1024;
    const int nkt = lower ? 24 : 12;
    const long o1r0 = (long)M0 + (m0 >> 11) * 1024 + (m0 & 2047);
    const uint32_t sb = sm_u32(dsc);

    float acc[4][4][4];
#pragma unroll
    for (int i = 0; i < 4; i++)
#pragma unroll
        for (int j = 0; j < 4; j++)
#pragma unroll
            for (int k = 0; k < 4; k++) acc[i][j][k] = 0.f;

    auto issue = [&](int t) {
        const hf* a; int kc, wr;
        if (t < 12) { a = o + (size_t)m0*HD;   kc = t*32;      wr = t*32; }
        else        { a = o + (size_t)o1r0*HD; kc = (t-12)*32; wr = 768 + (t-12)*32; }
        uint32_t s = sb + (t % 3) * OST;
        const hf* ap = a + kc;
        const hf* w = Wo + (size_t)wr*768 + n0;
        const int arow = tid >> 1, ak = (tid & 1) << 4;
        const size_t ao = (size_t)arow * HD + ak;
        const uint32_t ad = (uint32_t)(arow * GAS + ak) * 2;
        cpa16(s + ad, ap + ao);  cpa16(s + ad + 16, ap + ao + 8);
        const int brow = tid >> 3, bc = (tid & 7) << 4;
        const size_t bo_ = (size_t)brow * 768 + bc;
        const uint32_t bd = (uint32_t)(brow * GBS + bc) * 2 + 128*GAS*2;
        cpa16(s + bd, w + bo_);  cpa16(s + bd + 16, w + bo_ + 8);
        cp_commit();
    };

    issue(0); issue(1);
    for (int t = 0; t < nkt; t++) {
        if (t + 1 < nkt) cp_wait1(); else cp_wait0();
        __syncthreads();
        if (t + 2 < nkt) issue(t + 2);
        uint32_t s = sb + (t % 3) * OST;
        mma_ktile_h1(s, s + 128*GAS*2, mrow, ncol, lane, acc);
        __syncthreads();
    }

#pragma unroll
    for (int im = 0; im < 4; im++) {
        int r0g = m0 + mrow + im*16 + (lane >> 2);
#pragma unroll
        for (int f = 0; f < 4; f++) {
            int gcol = n0 + ncol + f*8 + ((lane & 3) << 1);
            float* d = acc[im][f];
#pragma unroll
            for (int hfi = 0; hfi < 2; hfi++) {
                int rr = r0g + hfi*8;
                out[(size_t)rr*768 + gcol]     = d[hfi*2]     + bo[gcol];
                out[(size_t)rr*768 + gcol + 1] = d[hfi*2 + 1] + bo[gcol + 1];
            }
        }
    }
}

// ---- merged flash attention: grid (24, 48); x%3==2 -> level1 ----
#define AS 72
#define KLB (64*AS*2)
#define SBUF (3*KLB)
#define ATTN_SMEM (3*SBUF)

__global__ __launch_bounds__(256, 2) void attn_mma(
    const bf* __restrict__ qh, const bf* __restrict__ ql,
    const bf* __restrict__ kh, const bf* __restrict__ kl,
    const hf* __restrict__ v, hf* __restrict__ om)
{
    extern __shared__ char smc[];
    bf* smem = (bf*)smc;
    const int tid = threadIdx.x, lane = tid & 31, warp = tid >> 5;
    const int lvl = (blockIdx.x % 3) == 2;
    const int qt = lvl ? (blockIdx.x / 3) : (blockIdx.x - blockIdx.x / 3);
    const int Nq = lvl ? N1 : N0;
    const size_t lbase = lvl ? (size_t)M0 * HD : 0;
    const int b = blockIdx.y / NH, h = blockIdx.y % NH;
    const int q0 = qt * 128;
    const size_t gb = lbase + (size_t)b*Nq*HD + (size_t)h*64;
    const int mrow = warp * 16;

    {
        const bf* Qh = qh + gb + (size_t)q0*HD;
        const bf* Ql = ql + gb + (size_t)q0*HD;
#pragma unroll
        for (int it = 0; it < 4; it++) {
            int i = tid + it*256, r = i >> 3, u = (i & 7)*8;
            *(uint4*)&smem[r*AS + u]          = *(const uint4*)&Qh[(size_t)r*HD + u];
            *(uint4*)&smem[128*AS + r*AS + u] = *(const uint4*)&Ql[(size_t)r*HD + u];
        }
    }
    __syncthreads();
    uint32_t qfh[4][4], qfl[4][4];
    {
        const uint32_t bh_ = sm_u32(smem), bl_ = sm_u32(smem) + 128*AS*2;
        int row = mrow + (lane & 15);
#pragma unroll
        for (int kk = 0; kk < 4; kk++) {
            uint32_t off = (uint32_t)(row*AS + kk*16 + ((lane >> 4) << 3))*2;
            ldsm4(qfh[kk], bh_ + off);
            ldsm4(qfl[kk], bl_ + off);
        }
    }
    __syncthreads();

    const uint32_t base0 = sm_u32(smc);
    auto kvload = [&](int s) {
        int kv = s * 64;
        const bf* Kh = kh + gb + (size_t)kv*HD;
        const bf* Kl = kl + gb + (size_t)kv*HD;
        const hf* V  = v  + gb + (size_t)kv*HD;
        uint32_t d = base0 + (s % 3) * SBUF;
#pragma unroll
        for (int it = 0; it < 2; it++) {
            int i = tid + it*256, r = i >> 3, u = (i & 7)*8;
            size_t go = (size_t)r*HD + u;
            uint32_t so = (uint32_t)(r*AS + u)*2;
            cpa16(d + so,         Kh + go);
            cpa16(d + KLB + so,   Kl + go);
            cpa16(d + 2*KLB + so, V  + go);
        }
        cp_commit();
    };

    float o[8][4];
#pragma unroll
    for (int f = 0; f < 8; f++)
#pragma unroll
        for (int k = 0; k < 4; k++) o[f][k] = 0.f;
    float mr0 = -1e30f, mr1 = -1e30f, lr0 = 0.f, lr1 = 0.f;

    const int S = Nq / 64;
    kvload(0); kvload(1);
    for (int t = 0; t < S; t++) {
        if (t + 1 < S) cp_wait1(); else cp_wait0();
        __syncthreads();
        if (t + 2 < S) kvload(t + 2);

        const uint32_t bb = base0 + (t % 3) * SBUF;
        const uint32_t kBH = bb, kBL = bb + KLB, vB = bb + 2*KLB;

        float s[8][4];
#pragma unroll
        for (int f = 0; f < 8; f++)
#pragma unroll
            for (int k = 0; k < 4; k++) s[f][k] = 0.f;
#pragma unroll
        for (int kk = 0; kk < 4; kk++) {
#pragma unroll
            for (int nf = 0; nf < 4; nf++) {
                uint32_t ad = (uint32_t)((nf*16 + (lane & 15))*AS + kk*16 +
                                         ((lane >> 4) << 3))*2;
                uint32_t kb[4], kl4[4];
                ldsm4(kb, kBH + ad); ldsm4(kl4, kBL + ad);
                mma_bf(s[nf*2],   qfh[kk], kb[0],  kb[2]);
                mma_bf(s[nf*2],   qfh[kk], kl4[0], kl4[2]);
                mma_bf(s[nf*2],   qfl[kk], kb[0],  kb[2]);
                mma_bf(s[nf*2+1], qfh[kk], kb[1],  kb[3]);
                mma_bf(s[nf*2+1], qfh[kk], kl4[1], kl4[3]);
                mma_bf(s[nf*2+1], qfl[kk], kb[1],  kb[3]);
            }
        }

        float mx0 = -1e30f, mx1 = -1e30f;
#pragma unroll
        for (int f = 0; f < 8; f++) {
            mx0 = fmaxf(mx0, fmaxf(s[f][0], s[f][1]));
            mx1 = fmaxf(mx1, fmaxf(s[f][2], s[f][3]));
        }
        mx0 = fmaxf(mx0, __shfl_xor_sync(~0u, mx0, 1));
        mx0 = fmaxf(mx0, __shfl_xor_sync(~0u, mx0, 2));
        mx1 = fmaxf(mx1, __shfl_xor_sync(~0u, mx1, 1));
        mx1 = fmaxf(mx1, __shfl_xor_sync(~0u, mx1, 2));
        float mn0 = fmaxf(mr0, mx0), mn1 = fmaxf(mr1, mx1);
        float c0 = __expf(mr0 - mn0), c1 = __expf(mr1 - mn1);
        float rs0 = 0.f, rs1 = 0.f;
#pragma unroll
        for (int f = 0; f < 8; f++) {
            s[f][0] = __expf(s[f][0] - mn0); s[f][1] = __expf(s[f][1] - mn0);
            s[f][2] = __expf(s[f][2] - mn1); s[f][3] = __expf(s[f][3] - mn1);
            rs0 += s[f][0] + s[f][1]; rs1 += s[f][2] + s[f][3];
        }
        rs0 += __shfl_xor_sync(~0u, rs0, 1); rs0 += __shfl_xor_sync(~0u, rs0, 2);
        rs1 += __shfl_xor_sync(~0u, rs1, 1); rs1 += __shfl_xor_sync(~0u, rs1, 2);
        lr0 = lr0*c0 + rs0; lr1 = lr1*c1 + rs1;
        mr0 = mn0; mr1 = mn1;
#pragma unroll
        for (int f = 0; f < 8; f++) {
            o[f][0] *= c0; o[f][1] *= c0; o[f][2] *= c1; o[f][3] *= c1;
        }

#pragma unroll
        for (int kk2 = 0; kk2 < 4; kk2++) {
            uint32_t pa[4];
            {
                int f0 = kk2*2;
                pa[0] = hpack(s[f0][0],   s[f0][1]);
                pa[1] = hpack(s[f0][2],   s[f0][3]);
                pa[2] = hpack(s[f0+1][0], s[f0+1][1]);
                pa[3] = hpack(s[f0+1][2], s[f0+1][3]);
            }
#pragma unroll
            for (int nf = 0; nf < 4; nf++) {
                uint32_t ad = (uint32_t)((kk2*16 + (lane & 15))*AS + nf*16 +
                                         ((lane >> 4) << 3))*2;
                uint32_t vb[4];
                ldsm4t(vb, vB + ad);
                mma_hf(o[nf*2],   pa, vb[0], vb[1]);
                mma_hf(o[nf*2+1], pa, vb[2], vb[3]);
            }
        }
    }

    float i0 = 1.f/lr0, i1 = 1.f/lr1;
    int rg = q0 + mrow + (lane >> 2);
#pragma unroll
    for (int f = 0; f < 8; f++) {
        int cc = f*8 + ((lane & 3) << 1);
        *(uint32_t*)(om + gb + (size_t)rg*HD + cc)     = hpack(o[f][0]*i0, o[f][1]*i0);
        *(uint32_t*)(om + gb + (size_t)(rg+8)*HD + cc) = hpack(o[f][2]*i1, o[f][3]*i1);
    }
}

__global__ void mask_kernel(float* __restrict__ out) {
    int i = blockIdx.x*blockDim.x + threadIdx.x;
    if (i < 2*N0) {
        int lvl = i >> 11, n = i & (N0 - 1);
        out[i] = (lvl == 0 || n < N1) ? 1.f : 0.f;
    }
}

extern "C" void kernel_launch(void* const* d_in, const int* in_sizes, int n_in,
                              void* d_out, int out_size)
{
    (void)in_sizes; (void)n_in; (void)out_size;
    const float* inp0 = (const float*)d_in[0];
    const float* inp1 = (const float*)d_in[1];
    const float* amask = (const float*)d_in[2];
    const float *Wq0 = (const float*)d_in[3],  *bq0 = (const float*)d_in[4];
    const float *Wk0 = (const float*)d_in[5],  *bk0 = (const float*)d_in[6];
    const float *Wv0 = (const float*)d_in[7],  *bv0 = (const float*)d_in[8];
    const float *Wq1 = (const float*)d_in[9],  *bq1 = (const float*)d_in[10];
    const float *Wk1 = (const float*)d_in[11], *bk1 = (const float*)d_in[12];
    const float *Wv1 = (const float*)d_in[13], *bv1 = (const float*)d_in[14];
    const float *Wo  = (const float*)d_in[15], *bo  = (const float*)d_in[16];
    float* out = (float*)d_out;

    bf *ih0,*il0,*ih1,*il1,*wh0,*wl0,*wh1,*wl1,*qh,*ql,*kh,*kl;
    hf *if0,*if1,*wv0f,*wv1f,*wo,*v,*o;
    cudaGetSymbolAddress((void**)&ih0,g_ih0); cudaGetSymbolAddress((void**)&il0,g_il0);
    cudaGetSymbolAddress((void**)&ih1,g_ih1); cudaGetSymbolAddress((void**)&il1,g_il1);
    cudaGetSymbolAddress((void**)&if0,g_if0); cudaGetSymbolAddress((void**)&if1,g_if1);
    cudaGetSymbolAddress((void**)&wh0,g_wh0); cudaGetSymbolAddress((void**)&wl0,g_wl0);
    cudaGetSymbolAddress((void**)&wh1,g_wh1); cudaGetSymbolAddress((void**)&wl1,g_wl1);
    cudaGetSymbolAddress((void**)&wv0f,g_wv0f); cudaGetSymbolAddress((void**)&wv1f,g_wv1f);
    cudaGetSymbolAddress((void**)&wo,g_wo);
    cudaGetSymbolAddress((void**)&qh,g_qh); cudaGetSymbolAddress((void**)&ql,g_ql);
    cudaGetSymbolAddress((void**)&kh,g_kh); cudaGetSymbolAddress((void**)&kl,g_kl);
    cudaGetSymbolAddress((void**)&v,g_v);   cudaGetSymbolAddress((void**)&o,g_o);

    cudaFuncSetAttribute(qkv_gemm, cudaFuncAttributeMaxDynamicSharedMemorySize, QKV_SMEM);
    cudaFuncSetAttribute(v_gemm,   cudaFuncAttributeMaxDynamicSharedMemorySize, V_SMEM);
    cudaFuncSetAttribute(out_gemm, cudaFuncAttributeMaxDynamicSharedMemorySize, OUT_SMEM);
    cudaFuncSetAttribute(attn_mma, cudaFuncAttributeMaxDynamicSharedMemorySize, ATTN_SMEM);

    // prep
    S3Jobs j3 = {{ {inp0, ih0, il0, if0}, {inp1, ih1, il1, if1} }};
    split3<<<dim3(2048,1,2), 256>>>(j3, M0*768);
    SJobs j0 = {{ {Wq0, wh0, wl0}, {Wk0, wh0 + 768*768, wl0 + 768*768} }};
    splitk<<<dim3(256,1,2), 256>>>(j0, 768*768);
    SJobs j1 = {{ {Wq1, wh1, wl1}, {Wk1, wh1 + 1536*768, wl1 + 1536*768} }};
    splitk<<<dim3(512,1,2), 256>>>(j1, 1536*768);
    CJobs jc = {{ {Wo, wo, 1536*768}, {Wv0, wv0f, 768*768}, {Wv1, wv1f, 1536*768} }};
    cvt3<<<dim3(512,1,3), 256>>>(jc);

    dim3 blk(256);
    QLv ql0 = {ih0, il0, wh0, wl0, bq0, bk0, 768, N0, 0, 0};
    QLv ql1 = {ih1, il1, wh1, wl1, bq1 + 384, bk1 + 384, 1536, N1, 384, M0};
    qkv_gemm<<<dim3(6, 192), blk, QKV_SMEM>>>(ql0, ql1, qh, ql, kh, kl, amask);

    VLv vl0 = {if0, wv0f, bv0, 768, 0, 0};
    VLv vl1 = {if1, wv1f, bv1 + 384, 1536, 384, M0};
    v_gemm<<<dim3(3, 192), blk, V_SMEM>>>(vl0, vl1, v);

    attn_mma<<<dim3(24, 48), blk, ATTN_SMEM>>>(qh, ql, kh, kl, v, o);

    out_gemm<<<dim3(6, 128), blk, OUT_SMEM>>>(o, wo, bo, out);
    mask_kernel<<<16, 256>>>(out + OUT_ELEMS);
}

// round 15
// speedup vs baseline: 1.0221x; 1.0221x over previous
#include <cuda_runtime.h>
#include <cuda_bf16.h>
#include <cuda_fp16.h>
#include <stdint.h>
typedef __nv_bfloat16 bf;
typedef __half hf;

#define B 8
#define N0 2048
#define N1 1024
#define HD 384
#define NH 6
#define M0 (B*N0)
#define M1 (B*N1)
#define MT (M0+M1)
#define OUT_ELEMS ((size_t)B*N0*768)

__device__ __align__(128) bf g_ih0[M0*768],  g_il0[M0*768];
__device__ __align__(128) bf g_ih1[M1*1536], g_il1[M1*1536];
__device__ __align__(128) hf g_if0[M0*768],  g_if1[M1*1536];
__device__ __align__(128) bf g_wh0[2][768*768],  g_wl0[2][768*768];
__device__ __align__(128) bf g_wh1[2][1536*768], g_wl1[2][1536*768];
__device__ __align__(128) hf g_wv0f[768*768], g_wv1f[1536*768], g_wo[1536*768];
__device__ __align__(128) bf g_qh[MT*HD], g_ql[MT*HD], g_kh[MT*HD], g_kl[MT*HD];
__device__ __align__(128) hf g_v[MT*HD];
__device__ __align__(128) hf g_o[MT*HD];

__device__ __forceinline__ uint32_t sm_u32(const void* p) {
    return (uint32_t)__cvta_generic_to_shared(p);
}
__device__ __forceinline__ void ldsm4(uint32_t r[4], uint32_t a) {
    asm volatile("ldmatrix.sync.aligned.m8n8.x4.shared.b16 {%0,%1,%2,%3}, [%4];"
        : "=r"(r[0]), "=r"(r[1]), "=r"(r[2]), "=r"(r[3]) : "r"(a));
}
__device__ __forceinline__ void ldsm4t(uint32_t r[4], uint32_t a) {
    asm volatile("ldmatrix.sync.aligned.m8n8.x4.trans.shared.b16 {%0,%1,%2,%3}, [%4];"
        : "=r"(r[0]), "=r"(r[1]), "=r"(r[2]), "=r"(r[3]) : "r"(a));
}
__device__ __forceinline__ void mma_bf(float d[4], const uint32_t a[4],
                                       uint32_t b0, uint32_t b1) {
    asm volatile("mma.sync.aligned.m16n8k16.row.col.f32.bf16.bf16.f32 "
        "{%0,%1,%2,%3}, {%4,%5,%6,%7}, {%8,%9}, {%0,%1,%2,%3};"
        : "+f"(d[0]), "+f"(d[1]), "+f"(d[2]), "+f"(d[3])
        : "r"(a[0]), "r"(a[1]), "r"(a[2]), "r"(a[3]), "r"(b0), "r"(b1));
}
__device__ __forceinline__ void mma_hf(float d[4], const uint32_t a[4],
                                       uint32_t b0, uint32_t b1) {
    asm volatile("mma.sync.aligned.m16n8k16.row.col.f32.f16.f16.f32 "
        "{%0,%1,%2,%3}, {%4,%5,%6,%7}, {%8,%9}, {%0,%1,%2,%3};"
        : "+f"(d[0]), "+f"(d[1]), "+f"(d[2]), "+f"(d[3])
        : "r"(a[0]), "r"(a[1]), "r"(a[2]), "r"(a[3]), "r"(b0), "r"(b1));
}
__device__ __forceinline__ uint32_t bpack(float lo, float hi) {
    __nv_bfloat162 t = __floats2bfloat162_rn(lo, hi);
    return *reinterpret_cast<uint32_t*>(&t);
}
__device__ __forceinline__ void fsplit(float x, float& h, float& l) {
    bf b = __float2bfloat16(x);
    h = __bfloat162float(b);
    l = x - h;
}
__device__ __forceinline__ uint32_t hpack(float lo, float hi) {
    __half2 t = __floats2half2_rn(lo, hi);
    return *reinterpret_cast<uint32_t*>(&t);
}
__device__ __forceinline__ void cpa16(uint32_t d, const void* s) {
    asm volatile("cp.async.cg.shared.global [%0], [%1], 16;" :: "r"(d), "l"(s));
}
__device__ __forceinline__ void cp_commit() { asm volatile("cp.async.commit_group;"); }
__device__ __forceinline__ void cp_wait0()  { asm volatile("cp.async.wait_group 0;"); }
__device__ __forceinline__ void cp_wait1()  { asm volatile("cp.async.wait_group 1;"); }

// ---- prep kernels ----
struct SJob  { const float* s; bf* h; bf* l; };
struct SJobs { SJob j[2]; };
__global__ void splitk(SJobs js, int n) {
    SJob J = js.j[blockIdx.z];
    for (int i = (blockIdx.x*256 + threadIdx.x)*4; i < n; i += gridDim.x*256*4) {
        float4 v = *(const float4*)(J.s + i);
        float h0,l0,h1,l1,h2,l2,h3,l3;
        fsplit(v.x,h0,l0); fsplit(v.y,h1,l1); fsplit(v.z,h2,l2); fsplit(v.w,h3,l3);
        *(uint2*)(J.h + i) = make_uint2(bpack(h0,h1), bpack(h2,h3));
        *(uint2*)(J.l + i) = make_uint2(bpack(l0,l1), bpack(l2,l3));
    }
}
struct S3Job  { const float* s; bf* h; bf* l; hf* f; };
struct S3Jobs { S3Job j[2]; };
__global__ void split3(S3Jobs js, int n) {
    S3Job J = js.j[blockIdx.z];
    for (int i = (blockIdx.x*256 + threadIdx.x)*4; i < n; i += gridDim.x*256*4) {
        float4 v = *(const float4*)(J.s + i);
        float h0,l0,h1,l1,h2,l2,h3,l3;
        fsplit(v.x,h0,l0); fsplit(v.y,h1,l1); fsplit(v.z,h2,l2); fsplit(v.w,h3,l3);
        *(uint2*)(J.h + i) = make_uint2(bpack(h0,h1), bpack(h2,h3));
        *(uint2*)(J.l + i) = make_uint2(bpack(l0,l1), bpack(l2,l3));
        *(uint2*)(J.f + i) = make_uint2(hpack(v.x,v.y), hpack(v.z,v.w));
    }
}
struct CJob  { const float* s; hf* d; int n; };
struct CJobs { CJob j[3]; };
__global__ void cvt3(CJobs js) {
    CJob J = js.j[blockIdx.z];
    for (int i = (blockIdx.x*256 + threadIdx.x)*4; i < J.n; i += gridDim.x*256*4) {
        float4 v = *(const float4*)(J.s + i);
        *(uint2*)(J.d + i) = make_uint2(hpack(v.x, v.y), hpack(v.z, v.w));
    }
}

// ---- tile constants ----
#define GAS 40
#define GBS 136
#define GEMM_SMEM ((2*128*GAS + 2*32*GBS) * 2 * 2)   // 75776 B -> 2 CTAs/SM

// bf16 3-term ktile
__device__ __forceinline__ void mma_ktile(
    uint32_t aBH, uint32_t aBL, uint32_t bBH, uint32_t bBL,
    int mrow, int ncol, int lane, float acc[4][4][4])
{
#pragma unroll
    for (int kk = 0; kk < 32; kk += 16) {
        uint32_t ah[4][4], al[4][4];
#pragma unroll
        for (int im = 0; im < 4; im++) {
            uint32_t ad = (uint32_t)((mrow + im*16 + (lane & 15)) * GAS +
                                     kk + ((lane >> 4) << 3)) * 2;
            ldsm4(ah[im], aBH + ad);
            ldsm4(al[im], aBL + ad);
        }
#pragma unroll
        for (int nf = 0; nf < 2; nf++) {
            uint32_t bd = (uint32_t)((kk + (lane & 15)) * GBS + ncol +
                                     nf*16 + ((lane >> 4) << 3)) * 2;
            uint32_t bh4[4], bl4[4];
            ldsm4t(bh4, bBH + bd);
            ldsm4t(bl4, bBL + bd);
#pragma unroll
            for (int im = 0; im < 4; im++) {
#pragma unroll
                for (int j = 0; j < 2; j++) {
                    float* d = acc[im][nf*2 + j];
                    mma_bf(d, ah[im], bh4[2*j], bh4[2*j+1]);
                    mma_bf(d, ah[im], bl4[2*j], bl4[2*j+1]);
                    mma_bf(d, al[im], bh4[2*j], bh4[2*j+1]);
                }
            }
        }
    }
}
__device__ __forceinline__ void gemm_cpa(
    const bf* aH, const bf* aL, int lda,
    const bf* wH, const bf* wL, int ldw,
    int tid, uint32_t dAh, uint32_t dAl, uint32_t dBh, uint32_t dBl)
{
    const int arow = tid >> 1, ak = (tid & 1) << 4;
    const size_t ao = (size_t)arow * lda + ak;
    const uint32_t ad = (uint32_t)(arow * GAS + ak) * 2;
    cpa16(dAh + ad, aH + ao);  cpa16(dAh + ad + 16, aH + ao + 8);
    cpa16(dAl + ad, aL + ao);  cpa16(dAl + ad + 16, aL + ao + 8);
    const int brow = tid >> 3, bc = (tid & 7) << 4;
    const size_t bo = (size_t)brow * ldw + bc;
    const uint32_t bd = (uint32_t)(brow * GBS + bc) * 2;
    cpa16(dBh + bd, wH + bo);  cpa16(dBh + bd + 16, wH + bo + 8);
    cpa16(dBl + bd, wL + bo);  cpa16(dBl + bd + 16, wL + bo + 8);
}

// ---- merged Q/K projection (round-13 2-stage core + level interleave) ----
// grid (6, 192); y%3==2 -> level1 (heavy), else level0.
struct QLv {
    const bf *Ah, *Al, *Wh, *Wl;
    const float *bq, *bk;
    int K, nseq, wOff;
    long orow;
};
__global__ __launch_bounds__(256, 2) void qkv_gemm(
    QLv L0, QLv L1,
    bf* __restrict__ qh, bf* __restrict__ ql,
    bf* __restrict__ kh, bf* __restrict__ kl,
    const float* __restrict__ mask)
{
    extern __shared__ bf ds[];
    bf* Ahs = ds;
    bf* Als = Ahs + 2*128*GAS;
    bf* Bhs = Als + 2*128*GAS;
    bf* Bls = Bhs + 2*32*GBS;

    const int tid = threadIdx.x, lane = tid & 31, warp = tid >> 5;
    const int y = blockIdx.y;
    const int lv = (y % 3) == 2;
    const QLv L = lv ? L1 : L0;
    const int myb = lv ? (y / 3) : (y - y / 3);
    const int sel = blockIdx.x / 3, n0 = (blockIdx.x % 3) * 128;
    const int m0 = myb * 128;
    const int K = L.K;
    const int mrow = (warp >> 2) * 64, ncol = (warp & 3) * 32;

    const bf* Wh = L.Wh + (size_t)sel * K * 768 + L.wOff + n0;
    const bf* Wl = L.Wl + (size_t)sel * K * 768 + L.wOff + n0;
    const float* bias = (sel == 0) ? L.bq : L.bk;
    bf* Ch = (sel == 0) ? qh : kh;
    bf* Cl = (sel == 0) ? ql : kl;
    const bf* aH = L.Ah + (size_t)m0 * K;
    const bf* aL = L.Al + (size_t)m0 * K;

    float acc[4][4][4];
#pragma unroll
    for (int i = 0; i < 4; i++)
#pragma unroll
        for (int j = 0; j < 4; j++)
#pragma unroll
            for (int k = 0; k < 4; k++) acc[i][j][k] = 0.f;

    gemm_cpa(aH, aL, K, Wh, Wl, 768, tid,
             sm_u32(Ahs), sm_u32(Als), sm_u32(Bhs), sm_u32(Bls));
    cp_commit();

    int buf = 0;
    for (int k0 = 0; k0 < K; k0 += 32) {
        cp_wait0();
        __syncthreads();
        if (k0 + 32 < K) {
            int nb = buf ^ 1;
            gemm_cpa(aH + k0 + 32, aL + k0 + 32, K,
                     Wh + (size_t)(k0 + 32)*768, Wl + (size_t)(k0 + 32)*768, 768, tid,
                     sm_u32(Ahs + nb*128*GAS), sm_u32(Als + nb*128*GAS),
                     sm_u32(Bhs + nb*32*GBS),  sm_u32(Bls + nb*32*GBS));
            cp_commit();
        }
        mma_ktile(sm_u32(Ahs + buf*128*GAS), sm_u32(Als + buf*128*GAS),
                  sm_u32(Bhs + buf*32*GBS),  sm_u32(Bls + buf*32*GBS),
                  mrow, ncol, lane, acc);
        buf ^= 1;
    }

#pragma unroll
    for (int im = 0; im < 4; im++) {
        int r0g = m0 + mrow + im*16 + (lane >> 2);
#pragma unroll
        for (int f = 0; f < 4; f++) {
            int gcol = n0 + ncol + f*8 + ((lane & 3) << 1);
            float* d = acc[im][f];
#pragma unroll
            for (int hfi = 0; hfi < 2; hfi++) {
                int rr = r0g + hfi*8;
                float x0 = d[hfi*2]     + bias[gcol];
                float x1 = d[hfi*2 + 1] + bias[gcol + 1];
                if (sel == 0) {
                    const float* mk = mask + (rr / L.nseq) * 64;
                    x0 = x0*0.125f + mk[gcol & 63];
                    x1 = x1*0.125f + mk[(gcol + 1) & 63];
                }
                size_t o = (size_t)(L.orow + rr) * HD + gcol;
                float h0,l0,h1,l1;
                fsplit(x0,h0,l0); fsplit(x1,h1,l1);
                *(uint32_t*)(Ch + o) = bpack(h0,h1);
                *(uint32_t*)(Cl + o) = bpack(l0,l1);
            }
        }
    }
}

// ---- fp16 1-term ktile ----
__device__ __forceinline__ void mma_ktile_h1(
    uint32_t aB, uint32_t bB, int mrow, int ncol, int lane, float acc[4][4][4])
{
#pragma unroll
    for (int kk = 0; kk < 32; kk += 16) {
        uint32_t ah[4][4];
#pragma unroll
        for (int im = 0; im < 4; im++) {
            uint32_t ad = (uint32_t)((mrow + im*16 + (lane & 15)) * GAS +
                                     kk + ((lane >> 4) << 3)) * 2;
            ldsm4(ah[im], aB + ad);
        }
#pragma unroll
        for (int nf = 0; nf < 2; nf++) {
            uint32_t bd = (uint32_t)((kk + (lane & 15)) * GBS + ncol +
                                     nf*16 + ((lane >> 4) << 3)) * 2;
            uint32_t b4[4];
            ldsm4t(b4, bB + bd);
#pragma unroll
            for (int im = 0; im < 4; im++) {
#pragma unroll
                for (int j = 0; j < 2; j++)
                    mma_hf(acc[im][nf*2 + j], ah[im], b4[2*j], b4[2*j+1]);
            }
        }
    }
}

#define VST ((128*GAS + 32*GBS) * 2)
#define V_SMEM (3*VST)

// ---- merged V projection: grid (3, 192), level interleave ----
struct VLv { const hf *A, *Wv; const float* bv; int K, wOff; long orow; };
__global__ __launch_bounds__(256, 2) void v_gemm(VLv L0, VLv L1, hf* __restrict__ v)
{
    extern __shared__ char dsc[];
    const int tid = threadIdx.x, lane = tid & 31, warp = tid >> 5;
    const int y = blockIdx.y;
    const int lv = (y % 3) == 2;
    const VLv L = lv ? L1 : L0;
    const int myb = lv ? (y / 3) : (y - y / 3);
    const int n0 = blockIdx.x * 128, m0 = myb * 128;
    const int K = L.K;
    const int mrow = (warp >> 2) * 64, ncol = (warp & 3) * 32;
    const uint32_t sb = sm_u32(dsc);

    float acc[4][4][4];
#pragma unroll
    for (int i = 0; i < 4; i++)
#pragma unroll
        for (int j = 0; j < 4; j++)
#pragma unroll
            for (int k = 0; k < 4; k++) acc[i][j][k] = 0.f;

    auto issue = [&](int t) {
        uint32_t s = sb + (t % 3) * VST;
        const hf* a = L.A + (size_t)m0 * K + t*32;
        const hf* w = L.Wv + (size_t)(t*32) * 768 + L.wOff + n0;
        const int arow = tid >> 1, ak = (tid & 1) << 4;
        const size_t ao = (size_t)arow * K + ak;
        const uint32_t ad = (uint32_t)(arow * GAS + ak) * 2;
        cpa16(s + ad, a + ao);  cpa16(s + ad + 16, a + ao + 8);
        const int brow = tid >> 3, bc = (tid & 7) << 4;
        const size_t bo = (size_t)brow * 768 + bc;
        const uint32_t bd = (uint32_t)(brow * GBS + bc) * 2 + 128*GAS*2;
        cpa16(s + bd, w + bo);  cpa16(s + bd + 16, w + bo + 8);
        cp_commit();
    };

    const int nkt = K / 32;
    issue(0); issue(1);
    for (int t = 0; t < nkt; t++) {
        if (t + 1 < nkt) cp_wait1(); else cp_wait0();
        __syncthreads();
        if (t + 2 < nkt) issue(t + 2);
        uint32_t s = sb + (t % 3) * VST;
        mma_ktile_h1(s, s + 128*GAS*2, mrow, ncol, lane, acc);
        __syncthreads();
    }

#pragma unroll
    for (int im = 0; im < 4; im++) {
        int r0g = m0 + mrow + im*16 + (lane >> 2);
#pragma unroll
        for (int f = 0; f < 4; f++) {
            int gcol = n0 + ncol + f*8 + ((lane & 3) << 1);
            float* d = acc[im][f];
#pragma unroll
            for (int hfi = 0; hfi < 2; hfi++) {
                int rr = r0g + hfi*8;
                *(uint32_t*)(v + (size_t)(L.orow + rr)*HD + gcol) =
                    hpack(d[hfi*2] + L.bv[gcol], d[hfi*2 + 1] + L.bv[gcol + 1]);
            }
        }
    }
}

#define OST VST
#define OUT_SMEM (3*OST)

// ---- output projection: grid (6, 128); y swizzled to mix 24/12-ktile CTAs ----
__global__ __launch_bounds__(256, 2) void out_gemm(
    const hf* __restrict__ o, const hf* __restrict__ Wo,
    const float* __restrict__ bo, float* __restrict__ out)
{
    extern __shared__ char dsc[];
    const int tid = threadIdx.x, lane = tid & 31, warp = tid >> 5;
    const int n0 = blockIdx.x * 128;
    const int yi = blockIdx.y >> 1;
    const int batch = yi >> 3, off = yi & 7;
    const int m0 = (batch * 16 + ((blockIdx.y & 1) ? 8 + off : off)) * 128;
    const int mrow = (warp >> 2) * 64, ncol = (warp & 3) * 32;

    const bool lower = (m0 & 2047) < 1024;
    const int nkt = lower ? 24 : 12;
    const long o1r0 = (long)M0 + (m0 >> 11) * 1024 + (m0 & 2047);
    const uint32_t sb = sm_u32(dsc);

    float acc[4][4][4];
#pragma unroll
    for (int i = 0; i < 4; i++)
#pragma unroll
        for (int j = 0; j < 4; j++)
#pragma unroll
            for (int k = 0; k < 4; k++) acc[i][j][k] = 0.f;

    auto issue = [&](int t) {
        const hf* a; int kc, wr;
        if (t < 12) { a = o + (size_t)m0*HD;   kc = t*32;      wr = t*32; }
        else        { a = o + (size_t)o1r0*HD; kc = (t-12)*32; wr = 768 + (t-12)*32; }
        uint32_t s = sb + (t % 3) * OST;
        const hf* ap = a + kc;
        const hf* w = Wo + (size_t)wr*768 + n0;
        const int arow = tid >> 1, ak = (tid & 1) << 4;
        const size_t ao = (size_t)arow * HD + ak;
        const uint32_t ad = (uint32_t)(arow * GAS + ak) * 2;
        cpa16(s + ad, ap + ao);  cpa16(s + ad + 16, ap + ao + 8);
        const int brow = tid >> 3, bc = (tid & 7) << 4;
        const size_t bo_ = (size_t)brow * 768 + bc;
        const uint32_t bd = (uint32_t)(brow * GBS + bc) * 2 + 128*GAS*2;
        cpa16(s + bd, w + bo_);  cpa16(s + bd + 16, w + bo_ + 8);
        cp_commit();
    };

    issue(0); issue(1);
    for (int t = 0; t < nkt; t++) {
        if (t + 1 < nkt) cp_wait1(); else cp_wait0();
        __syncthreads();
        if (t + 2 < nkt) issue(t + 2);
        uint32_t s = sb + (t % 3) * OST;
        mma_ktile_h1(s, s + 128*GAS*2, mrow, ncol, lane, acc);
        __syncthreads();
    }

#pragma unroll
    for (int im = 0; im < 4; im++) {
        int r0g = m0 + mrow + im*16 + (lane >> 2);
#pragma unroll
        for (int f = 0; f < 4; f++) {
            int gcol = n0 + ncol + f*8 + ((lane & 3) << 1);
            float* d = acc[im][f];
#pragma unroll
            for (int hfi = 0; hfi < 2; hfi++) {
                int rr = r0g + hfi*8;
                out[(size_t)rr*768 + gcol]     = d[hfi*2]     + bo[gcol];
                out[(size_t)rr*768 + gcol + 1] = d[hfi*2 + 1] + bo[gcol + 1];
            }
        }
    }
}

// ---- merged flash attention: grid (24, 48); x%3==2 -> level1 ----
#define AS 72
#define KLB (64*AS*2)
#define SBUF (3*KLB)
#define ATTN_SMEM (3*SBUF)

__global__ __launch_bounds__(256, 2) void attn_mma(
    const bf* __restrict__ qh, const bf* __restrict__ ql,
    const bf* __restrict__ kh, const bf* __restrict__ kl,
    const hf* __restrict__ v, hf* __restrict__ om)
{
    extern __shared__ char smc[];
    bf* smem = (bf*)smc;
    const int tid = threadIdx.x, lane = tid & 31, warp = tid >> 5;
    const int lvl = (blockIdx.x % 3) == 2;
    const int qt = lvl ? (blockIdx.x / 3) : (blockIdx.x - blockIdx.x / 3);
    const int Nq = lvl ? N1 : N0;
    const size_t lbase = lvl ? (size_t)M0 * HD : 0;
    const int b = blockIdx.y / NH, h = blockIdx.y % NH;
    const int q0 = qt * 128;
    const size_t gb = lbase + (size_t)b*Nq*HD + (size_t)h*64;
    const int mrow = warp * 16;

    {
        const bf* Qh = qh + gb + (size_t)q0*HD;
        const bf* Ql = ql + gb + (size_t)q0*HD;
#pragma unroll
        for (int it = 0; it < 4; it++) {
            int i = tid + it*256, r = i >> 3, u = (i & 7)*8;
            *(uint4*)&smem[r*AS + u]          = *(const uint4*)&Qh[(size_t)r*HD + u];
            *(uint4*)&smem[128*AS + r*AS + u] = *(const uint4*)&Ql[(size_t)r*HD + u];
        }
    }
    __syncthreads();
    uint32_t qfh[4][4], qfl[4][4];
    {
        const uint32_t bh_ = sm_u32(smem), bl_ = sm_u32(smem) + 128*AS*2;
        int row = mrow + (lane & 15);
#pragma unroll
        for (int kk = 0; kk < 4; kk++) {
            uint32_t off = (uint32_t)(row*AS + kk*16 + ((lane >> 4) << 3))*2;
            ldsm4(qfh[kk], bh_ + off);
            ldsm4(qfl[kk], bl_ + off);
        }
    }
    __syncthreads();

    const uint32_t base0 = sm_u32(smc);
    auto kvload = [&](int s) {
        int kv = s * 64;
        const bf* Kh = kh + gb + (size_t)kv*HD;
        const bf* Kl = kl + gb + (size_t)kv*HD;
        const hf* V  = v  + gb + (size_t)kv*HD;
        uint32_t d = base0 + (s % 3) * SBUF;
#pragma unroll
        for (int it = 0; it < 2; it++) {
            int i = tid + it*256, r = i >> 3, u = (i & 7)*8;
            size_t go = (size_t)r*HD + u;
            uint32_t so = (uint32_t)(r*AS + u)*2;
            cpa16(d + so,         Kh + go);
            cpa16(d + KLB + so,   Kl + go);
            cpa16(d + 2*KLB + so, V  + go);
        }
        cp_commit();
    };

    float o[8][4];
#pragma unroll
    for (int f = 0; f < 8; f++)
#pragma unroll
        for (int k = 0; k < 4; k++) o[f][k] = 0.f;
    float mr0 = -1e30f, mr1 = -1e30f, lr0 = 0.f, lr1 = 0.f;

    const int S = Nq / 64;
    kvload(0); kvload(1);
    for (int t = 0; t < S; t++) {
        if (t + 1 < S) cp_wait1(); else cp_wait0();
        __syncthreads();
        if (t + 2 < S) kvload(t + 2);

        const uint32_t bb = base0 + (t % 3) * SBUF;
        const uint32_t kBH = bb, kBL = bb + KLB, vB = bb + 2*KLB;

        float s[8][4];
#pragma unroll
        for (int f = 0; f < 8; f++)
#pragma unroll
            for (int k = 0; k < 4; k++) s[f][k] = 0.f;
#pragma unroll
        for (int kk = 0; kk < 4; kk++) {
#pragma unroll
            for (int nf = 0; nf < 4; nf++) {
                uint32_t ad = (uint32_t)((nf*16 + (lane & 15))*AS + kk*16 +
                                         ((lane >> 4) << 3))*2;
                uint32_t kb[4], kl4[4];
                ldsm4(kb, kBH + ad); ldsm4(kl4, kBL + ad);
                mma_bf(s[nf*2],   qfh[kk], kb[0],  kb[2]);
                mma_bf(s[nf*2],   qfh[kk], kl4[0], kl4[2]);
                mma_bf(s[nf*2],   qfl[kk], kb[0],  kb[2]);
                mma_bf(s[nf*2+1], qfh[kk], kb[1],  kb[3]);
                mma_bf(s[nf*2+1], qfh[kk], kl4[1], kl4[3]);
                mma_bf(s[nf*2+1], qfl[kk], kb[1],  kb[3]);
            }
        }

        float mx0 = -1e30f, mx1 = -1e30f;
#pragma unroll
        for (int f = 0; f < 8; f++) {
            mx0 = fmaxf(mx0, fmaxf(s[f][0], s[f][1]));
            mx1 = fmaxf(mx1, fmaxf(s[f][2], s[f][3]));
        }
        mx0 = fmaxf(mx0, __shfl_xor_sync(~0u, mx0, 1));
        mx0 = fmaxf(mx0, __shfl_xor_sync(~0u, mx0, 2));
        mx1 = fmaxf(mx1, __shfl_xor_sync(~0u, mx1, 1));
        mx1 = fmaxf(mx1, __shfl_xor_sync(~0u, mx1, 2));
        float mn0 = fmaxf(mr0, mx0), mn1 = fmaxf(mr1, mx1);
        float c0 = __expf(mr0 - mn0), c1 = __expf(mr1 - mn1);
        float rs0 = 0.f, rs1 = 0.f;
#pragma unroll
        for (int f = 0; f < 8; f++) {
            s[f][0] = __expf(s[f][0] - mn0); s[f][1] = __expf(s[f][1] - mn0);
            s[f][2] = __expf(s[f][2] - mn1); s[f][3] = __expf(s[f][3] - mn1);
            rs0 += s[f][0] + s[f][1]; rs1 += s[f][2] + s[f][3];
        }
        rs0 += __shfl_xor_sync(~0u, rs0, 1); rs0 += __shfl_xor_sync(~0u, rs0, 2);
        rs1 += __shfl_xor_sync(~0u, rs1, 1); rs1 += __shfl_xor_sync(~0u, rs1, 2);
        lr0 = lr0*c0 + rs0; lr1 = lr1*c1 + rs1;
        mr0 = mn0; mr1 = mn1;
#pragma unroll
        for (int f = 0; f < 8; f++) {
            o[f][0] *= c0; o[f][1] *= c0; o[f][2] *= c1; o[f][3] *= c1;
        }

#pragma unroll
        for (int kk2 = 0; kk2 < 4; kk2++) {
            uint32_t pa[4];
            {
                int f0 = kk2*2;
                pa[0] = hpack(s[f0][0],   s[f0][1]);
                pa[1] = hpack(s[f0][2],   s[f0][3]);
                pa[2] = hpack(s[f0+1][0], s[f0+1][1]);
                pa[3] = hpack(s[f0+1][2], s[f0+1][3]);
            }
#pragma unroll
            for (int nf = 0; nf < 4; nf++) {
                uint32_t ad = (uint32_t)((kk2*16 + (lane & 15))*AS + nf*16 +
                                         ((lane >> 4) << 3))*2;
                uint32_t vb[4];
                ldsm4t(vb, vB + ad);
                mma_hf(o[nf*2],   pa, vb[0], vb[1]);
                mma_hf(o[nf*2+1], pa, vb[2], vb[3]);
            }
        }
    }

    float i0 = 1.f/lr0, i1 = 1.f/lr1;
    int rg = q0 + mrow + (lane >> 2);
#pragma unroll
    for (int f = 0; f < 8; f++) {
        int cc = f*8 + ((lane & 3) << 1);
        *(uint32_t*)(om + gb + (size_t)rg*HD + cc)     = hpack(o[f][0]*i0, o[f][1]*i0);
        *(uint32_t*)(om + gb + (size_t)(rg+8)*HD + cc) = hpack(o[f][2]*i1, o[f][3]*i1);
    }
}

__global__ void mask_kernel(float* __restrict__ out) {
    int i = blockIdx.x*blockDim.x + threadIdx.x;
    if (i < 2*N0) {
        int lvl = i >> 11, n = i & (N0 - 1);
        out[i] = (lvl == 0 || n < N1) ? 1.f : 0.f;
    }
}

extern "C" void kernel_launch(void* const* d_in, const int* in_sizes, int n_in,
                              void* d_out, int out_size)
{
    (void)in_sizes; (void)n_in; (void)out_size;
    const float* inp0 = (const float*)d_in[0];
    const float* inp1 = (const float*)d_in[1];
    const float* amask = (const float*)d_in[2];
    const float *Wq0 = (const float*)d_in[3],  *bq0 = (const float*)d_in[4];
    const float *Wk0 = (const float*)d_in[5],  *bk0 = (const float*)d_in[6];
    const float *Wv0 = (const float*)d_in[7],  *bv0 = (const float*)d_in[8];
    const float *Wq1 = (const float*)d_in[9],  *bq1 = (const float*)d_in[10];
    const float *Wk1 = (const float*)d_in[11], *bk1 = (const float*)d_in[12];
    const float *Wv1 = (const float*)d_in[13], *bv1 = (const float*)d_in[14];
    const float *Wo  = (const float*)d_in[15], *bo  = (const float*)d_in[16];
    float* out = (float*)d_out;

    bf *ih0,*il0,*ih1,*il1,*wh0,*wl0,*wh1,*wl1,*qh,*ql,*kh,*kl;
    hf *if0,*if1,*wv0f,*wv1f,*wo,*v,*o;
    cudaGetSymbolAddress((void**)&ih0,g_ih0); cudaGetSymbolAddress((void**)&il0,g_il0);
    cudaGetSymbolAddress((void**)&ih1,g_ih1); cudaGetSymbolAddress((void**)&il1,g_il1);
    cudaGetSymbolAddress((void**)&if0,g_if0); cudaGetSymbolAddress((void**)&if1,g_if1);
    cudaGetSymbolAddress((void**)&wh0,g_wh0); cudaGetSymbolAddress((void**)&wl0,g_wl0);
    cudaGetSymbolAddress((void**)&wh1,g_wh1); cudaGetSymbolAddress((void**)&wl1,g_wl1);
    cudaGetSymbolAddress((void**)&wv0f,g_wv0f); cudaGetSymbolAddress((void**)&wv1f,g_wv1f);
    cudaGetSymbolAddress((void**)&wo,g_wo);
    cudaGetSymbolAddress((void**)&qh,g_qh); cudaGetSymbolAddress((void**)&ql,g_ql);
    cudaGetSymbolAddress((void**)&kh,g_kh); cudaGetSymbolAddress((void**)&kl,g_kl);
    cudaGetSymbolAddress((void**)&v,g_v);   cudaGetSymbolAddress((void**)&o,g_o);

    cudaFuncSetAttribute(qkv_gemm, cudaFuncAttributeMaxDynamicSharedMemorySize, GEMM_SMEM);
    cudaFuncSetAttribute(v_gemm,   cudaFuncAttributeMaxDynamicSharedMemorySize, V_SMEM);
    cudaFuncSetAttribute(out_gemm, cudaFuncAttributeMaxDynamicSharedMemorySize, OUT_SMEM);
    cudaFuncSetAttribute(attn_mma, cudaFuncAttributeMaxDynamicSharedMemorySize, ATTN_SMEM);

    // prep
    S3Jobs j3 = {{ {inp0, ih0, il0, if0}, {inp1, ih1, il1, if1} }};
    split3<<<dim3(2048,1,2), 256>>>(j3, M0*768);
    SJobs j0 = {{ {Wq0, wh0, wl0}, {Wk0, wh0 + 768*768, wl0 + 768*768} }};
    splitk<<<dim3(256,1,2), 256>>>(j0, 768*768);
    SJobs j1 = {{ {Wq1, wh1, wl1}, {Wk1, wh1 + 1536*768, wl1 + 1536*768} }};
    splitk<<<dim3(512,1,2), 256>>>(j1, 1536*768);
    CJobs jc = {{ {Wo, wo, 1536*768}, {Wv0, wv0f, 768*768}, {Wv1, wv1f, 1536*768} }};
    cvt3<<<dim3(512,1,3), 256>>>(jc);

    dim3 blk(256);
    QLv ql0 = {ih0, il0, wh0, wl0, bq0, bk0, 768, N0, 0, 0};
    QLv ql1 = {ih1, il1, wh1, wl1, bq1 + 384, bk1 + 384, 1536, N1, 384, M0};
    qkv_gemm<<<dim3(6, 192), blk, GEMM_SMEM>>>(ql0, ql1, qh, ql, kh, kl, amask);

    VLv vl0 = {if0, wv0f, bv0, 768, 0, 0};
    VLv vl1 = {if1, wv1f, bv1 + 384, 1536, 384, M0};
    v_gemm<<<dim3(3, 192), blk, V_SMEM>>>(vl0, vl1, v);

    attn_mma<<<dim3(24, 48), blk, ATTN_SMEM>>>(qh, ql, kh, kl, v, o);

    out_gemm<<<dim3(6, 128), blk, OUT_SMEM>>>(o, wo, bo, out);
    mask_kernel<<<16, 256>>>(out + OUT_ELEMS);
}

// round 16
// speedup vs baseline: 1.0412x; 1.0187x over previous
#include <cuda_runtime.h>
#include <cuda_bf16.h>
#include <cuda_fp16.h>
#include <stdint.h>
typedef __nv_bfloat16 bf;
typedef __half hf;

#define B 8
#define N0 2048
#define N1 1024
#define HD 384
#define NH 6
#define M0 (B*N0)
#define M1 (B*N1)
#define MT (M0+M1)
#define OUT_ELEMS ((size_t)B*N0*768)

__device__ __align__(128) bf g_ih0[M0*768],  g_il0[M0*768];
__device__ __align__(128) bf g_ih1[M1*1536], g_il1[M1*1536];
__device__ __align__(128) hf g_if0[M0*768],  g_if1[M1*1536];
__device__ __align__(128) bf g_wh0[2][768*768],  g_wl0[2][768*768];
__device__ __align__(128) bf g_wh1[2][1536*768], g_wl1[2][1536*768];
__device__ __align__(128) hf g_wv0f[768*768], g_wv1f[1536*768], g_wo[1536*768];
__device__ __align__(128) bf g_qh[MT*HD], g_ql[MT*HD], g_kh[MT*HD], g_kl[MT*HD];
__device__ __align__(128) hf g_v[MT*HD];
__device__ __align__(128) hf g_o[MT*HD];

__device__ __forceinline__ uint32_t sm_u32(const void* p) {
    return (uint32_t)__cvta_generic_to_shared(p);
}
__device__ __forceinline__ void ldsm4(uint32_t r[4], uint32_t a) {
    asm volatile("ldmatrix.sync.aligned.m8n8.x4.shared.b16 {%0,%1,%2,%3}, [%4];"
        : "=r"(r[0]), "=r"(r[1]), "=r"(r[2]), "=r"(r[3]) : "r"(a));
}
__device__ __forceinline__ void ldsm4t(uint32_t r[4], uint32_t a) {
    asm volatile("ldmatrix.sync.aligned.m8n8.x4.trans.shared.b16 {%0,%1,%2,%3}, [%4];"
        : "=r"(r[0]), "=r"(r[1]), "=r"(r[2]), "=r"(r[3]) : "r"(a));
}
__device__ __forceinline__ void mma_bf(float d[4], const uint32_t a[4],
                                       uint32_t b0, uint32_t b1) {
    asm volatile("mma.sync.aligned.m16n8k16.row.col.f32.bf16.bf16.f32 "
        "{%0,%1,%2,%3}, {%4,%5,%6,%7}, {%8,%9}, {%0,%1,%2,%3};"
        : "+f"(d[0]), "+f"(d[1]), "+f"(d[2]), "+f"(d[3])
        : "r"(a[0]), "r"(a[1]), "r"(a[2]), "r"(a[3]), "r"(b0), "r"(b1));
}
__device__ __forceinline__ void mma_hf(float d[4], const uint32_t a[4],
                                       uint32_t b0, uint32_t b1) {
    asm volatile("mma.sync.aligned.m16n8k16.row.col.f32.f16.f16.f32 "
        "{%0,%1,%2,%3}, {%4,%5,%6,%7}, {%8,%9}, {%0,%1,%2,%3};"
        : "+f"(d[0]), "+f"(d[1]), "+f"(d[2]), "+f"(d[3])
        : "r"(a[0]), "r"(a[1]), "r"(a[2]), "r"(a[3]), "r"(b0), "r"(b1));
}
__device__ __forceinline__ uint32_t bpack(float lo, float hi) {
    __nv_bfloat162 t = __floats2bfloat162_rn(lo, hi);
    return *reinterpret_cast<uint32_t*>(&t);
}
__device__ __forceinline__ void fsplit(float x, float& h, float& l) {
    bf b = __float2bfloat16(x);
    h = __bfloat162float(b);
    l = x - h;
}
__device__ __forceinline__ uint32_t hpack(float lo, float hi) {
    __half2 t = __floats2half2_rn(lo, hi);
    return *reinterpret_cast<uint32_t*>(&t);
}
__device__ __forceinline__ void cpa16(uint32_t d, const void* s) {
    asm volatile("cp.async.cg.shared.global [%0], [%1], 16;" :: "r"(d), "l"(s));
}
__device__ __forceinline__ void cp_commit() { asm volatile("cp.async.commit_group;"); }
__device__ __forceinline__ void cp_wait0()  { asm volatile("cp.async.wait_group 0;"); }
__device__ __forceinline__ void cp_wait1()  { asm volatile("cp.async.wait_group 1;"); }

// ---- prep kernels ----
struct SJob  { const float* s; bf* h; bf* l; };
struct SJobs { SJob j[2]; };
__global__ void splitk(SJobs js, int n) {
    SJob J = js.j[blockIdx.z];
    for (int i = (blockIdx.x*256 + threadIdx.x)*4; i < n; i += gridDim.x*256*4) {
        float4 v = *(const float4*)(J.s + i);
        float h0,l0,h1,l1,h2,l2,h3,l3;
        fsplit(v.x,h0,l0); fsplit(v.y,h1,l1); fsplit(v.z,h2,l2); fsplit(v.w,h3,l3);
        *(uint2*)(J.h + i) = make_uint2(bpack(h0,h1), bpack(h2,h3));
        *(uint2*)(J.l + i) = make_uint2(bpack(l0,l1), bpack(l2,l3));
    }
}
struct S3Job  { const float* s; bf* h; bf* l; hf* f; };
struct S3Jobs { S3Job j[2]; };
__global__ void split3(S3Jobs js, int n) {
    S3Job J = js.j[blockIdx.z];
    for (int i = (blockIdx.x*256 + threadIdx.x)*4; i < n; i += gridDim.x*256*4) {
        float4 v = *(const float4*)(J.s + i);
        float h0,l0,h1,l1,h2,l2,h3,l3;
        fsplit(v.x,h0,l0); fsplit(v.y,h1,l1); fsplit(v.z,h2,l2); fsplit(v.w,h3,l3);
        *(uint2*)(J.h + i) = make_uint2(bpack(h0,h1), bpack(h2,h3));
        *(uint2*)(J.l + i) = make_uint2(bpack(l0,l1), bpack(l2,l3));
        *(uint2*)(J.f + i) = make_uint2(hpack(v.x,v.y), hpack(v.z,v.w));
    }
}
struct CJob  { const float* s; hf* d; int n; };
struct CJobs { CJob j[3]; };
__global__ void cvt3(CJobs js) {
    CJob J = js.j[blockIdx.z];
    for (int i = (blockIdx.x*256 + threadIdx.x)*4; i < J.n; i += gridDim.x*256*4) {
        float4 v = *(const float4*)(J.s + i);
        *(uint2*)(J.d + i) = make_uint2(hpack(v.x, v.y), hpack(v.z, v.w));
    }
}

// ---- tile constants ----
#define GAS 40
#define GBS 136
#define GEMM_SMEM ((2*128*GAS + 2*32*GBS) * 2 * 2)   // 75776 B -> 2 CTAs/SM

// bf16 3-term ktile
__device__ __forceinline__ void mma_ktile(
    uint32_t aBH, uint32_t aBL, uint32_t bBH, uint32_t bBL,
    int mrow, int ncol, int lane, float acc[4][4][4])
{
#pragma unroll
    for (int kk = 0; kk < 32; kk += 16) {
        uint32_t ah[4][4], al[4][4];
#pragma unroll
        for (int im = 0; im < 4; im++) {
            uint32_t ad = (uint32_t)((mrow + im*16 + (lane & 15)) * GAS +
                                     kk + ((lane >> 4) << 3)) * 2;
            ldsm4(ah[im], aBH + ad);
            ldsm4(al[im], aBL + ad);
        }
#pragma unroll
        for (int nf = 0; nf < 2; nf++) {
            uint32_t bd = (uint32_t)((kk + (lane & 15)) * GBS + ncol +
                                     nf*16 + ((lane >> 4) << 3)) * 2;
            uint32_t bh4[4], bl4[4];
            ldsm4t(bh4, bBH + bd);
            ldsm4t(bl4, bBL + bd);
#pragma unroll
            for (int im = 0; im < 4; im++) {
#pragma unroll
                for (int j = 0; j < 2; j++) {
                    float* d = acc[im][nf*2 + j];
                    mma_bf(d, ah[im], bh4[2*j], bh4[2*j+1]);
                    mma_bf(d, ah[im], bl4[2*j], bl4[2*j+1]);
                    mma_bf(d, al[im], bh4[2*j], bh4[2*j+1]);
                }
            }
        }
    }
}
// fp16 1-term ktile
__device__ __forceinline__ void mma_ktile_h1(
    uint32_t aB, uint32_t bB, int mrow, int ncol, int lane, float acc[4][4][4])
{
#pragma unroll
    for (int kk = 0; kk < 32; kk += 16) {
        uint32_t ah[4][4];
#pragma unroll
        for (int im = 0; im < 4; im++) {
            uint32_t ad = (uint32_t)((mrow + im*16 + (lane & 15)) * GAS +
                                     kk + ((lane >> 4) << 3)) * 2;
            ldsm4(ah[im], aB + ad);
        }
#pragma unroll
        for (int nf = 0; nf < 2; nf++) {
            uint32_t bd = (uint32_t)((kk + (lane & 15)) * GBS + ncol +
                                     nf*16 + ((lane >> 4) << 3)) * 2;
            uint32_t b4[4];
            ldsm4t(b4, bB + bd);
#pragma unroll
            for (int im = 0; im < 4; im++) {
#pragma unroll
                for (int j = 0; j < 2; j++)
                    mma_hf(acc[im][nf*2 + j], ah[im], b4[2*j], b4[2*j+1]);
            }
        }
    }
}
__device__ __forceinline__ void gemm_cpa(
    const bf* aH, const bf* aL, int lda,
    const bf* wH, const bf* wL, int ldw,
    int tid, uint32_t dAh, uint32_t dAl, uint32_t dBh, uint32_t dBl)
{
    const int arow = tid >> 1, ak = (tid & 1) << 4;
    const size_t ao = (size_t)arow * lda + ak;
    const uint32_t ad = (uint32_t)(arow * GAS + ak) * 2;
    cpa16(dAh + ad, aH + ao);  cpa16(dAh + ad + 16, aH + ao + 8);
    cpa16(dAl + ad, aL + ao);  cpa16(dAl + ad + 16, aL + ao + 8);
    const int brow = tid >> 3, bc = (tid & 7) << 4;
    const size_t bo = (size_t)brow * ldw + bc;
    const uint32_t bd = (uint32_t)(brow * GBS + bc) * 2;
    cpa16(dBh + bd, wH + bo);  cpa16(dBh + bd + 16, wH + bo + 8);
    cpa16(dBl + bd, wL + bo);  cpa16(dBl + bd + 16, wL + bo + 8);
}

// ---- merged Q/K/V projection (round-13 core, v folded in): grid (9, 192) ----
// sel = bx/3: 0=q, 1=k (bf16 3-term), 2=v (fp16 1-term). y<128 -> level0.
struct QLv {
    const bf *Ah, *Al, *Wh, *Wl;
    const hf *Af, *Wvf;
    const float *bq, *bk, *bv;
    int K, nseq, wOff;
    long orow;
};
__global__ __launch_bounds__(256, 2) void qkv_gemm(
    QLv L0, QLv L1,
    bf* __restrict__ qh, bf* __restrict__ ql,
    bf* __restrict__ kh, bf* __restrict__ kl,
    hf* __restrict__ v, const float* __restrict__ mask)
{
    extern __shared__ bf ds[];
    bf* Ahs = ds;
    bf* Als = Ahs + 2*128*GAS;
    bf* Bhs = Als + 2*128*GAS;
    bf* Bls = Bhs + 2*32*GBS;

    const int tid = threadIdx.x, lane = tid & 31, warp = tid >> 5;
    const QLv L = (blockIdx.y < 128) ? L0 : L1;
    const int myb = (blockIdx.y < 128) ? blockIdx.y : blockIdx.y - 128;
    const int sel = blockIdx.x / 3, n0 = (blockIdx.x % 3) * 128;
    const int m0 = myb * 128;
    const int K = L.K;
    const int mrow = (warp >> 2) * 64, ncol = (warp & 3) * 32;

    float acc[4][4][4];
#pragma unroll
    for (int i = 0; i < 4; i++)
#pragma unroll
        for (int j = 0; j < 4; j++)
#pragma unroll
            for (int k = 0; k < 4; k++) acc[i][j][k] = 0.f;

    if (sel == 2) {
        // ---- V path: fp16 single, 1 MMA/k16, double-buffered in Ah/Bh ----
        const hf* A = L.Af + (size_t)m0 * K;
        const hf* W = L.Wvf + L.wOff + n0;
        auto issueV = [&](int t, int b) {
            uint32_t dA = sm_u32(Ahs + b*128*GAS);
            uint32_t dB = sm_u32(Bhs + b*32*GBS);
            const hf* ap = A + t*32;
            const hf* wp = W + (size_t)(t*32) * 768;
            const int arow = tid >> 1, ak = (tid & 1) << 4;
            const size_t ao = (size_t)arow * K + ak;
            const uint32_t ad = (uint32_t)(arow * GAS + ak) * 2;
            cpa16(dA + ad, ap + ao);  cpa16(dA + ad + 16, ap + ao + 8);
            const int brow = tid >> 3, bc = (tid & 7) << 4;
            const size_t bo = (size_t)brow * 768 + bc;
            const uint32_t bd = (uint32_t)(brow * GBS + bc) * 2;
            cpa16(dB + bd, wp + bo);  cpa16(dB + bd + 16, wp + bo + 8);
            cp_commit();
        };
        issueV(0, 0);
        int buf = 0;
        const int nkt = K / 32;
        for (int t = 0; t < nkt; t++) {
            cp_wait0();
            __syncthreads();
            if (t + 1 < nkt) issueV(t + 1, buf ^ 1);
            mma_ktile_h1(sm_u32(Ahs + buf*128*GAS), sm_u32(Bhs + buf*32*GBS),
                         mrow, ncol, lane, acc);
            buf ^= 1;
        }
#pragma unroll
        for (int im = 0; im < 4; im++) {
            int r0g = m0 + mrow + im*16 + (lane >> 2);
#pragma unroll
            for (int f = 0; f < 4; f++) {
                int gcol = n0 + ncol + f*8 + ((lane & 3) << 1);
                float* d = acc[im][f];
#pragma unroll
                for (int hfi = 0; hfi < 2; hfi++) {
                    int rr = r0g + hfi*8;
                    *(uint32_t*)(v + (size_t)(L.orow + rr)*HD + gcol) =
                        hpack(d[hfi*2] + L.bv[gcol], d[hfi*2 + 1] + L.bv[gcol + 1]);
                }
            }
        }
        return;
    }

    // ---- Q/K path: bf16 3-term (round-13 verbatim) ----
    const bf* Wh = L.Wh + (size_t)sel * K * 768 + L.wOff + n0;
    const bf* Wl = L.Wl + (size_t)sel * K * 768 + L.wOff + n0;
    const float* bias = (sel == 0) ? L.bq : L.bk;
    bf* Ch = (sel == 0) ? qh : kh;
    bf* Cl = (sel == 0) ? ql : kl;
    const bf* aH = L.Ah + (size_t)m0 * K;
    const bf* aL = L.Al + (size_t)m0 * K;

    gemm_cpa(aH, aL, K, Wh, Wl, 768, tid,
             sm_u32(Ahs), sm_u32(Als), sm_u32(Bhs), sm_u32(Bls));
    cp_commit();

    int buf = 0;
    for (int k0 = 0; k0 < K; k0 += 32) {
        cp_wait0();
        __syncthreads();
        if (k0 + 32 < K) {
            int nb = buf ^ 1;
            gemm_cpa(aH + k0 + 32, aL + k0 + 32, K,
                     Wh + (size_t)(k0 + 32)*768, Wl + (size_t)(k0 + 32)*768, 768, tid,
                     sm_u32(Ahs + nb*128*GAS), sm_u32(Als + nb*128*GAS),
                     sm_u32(Bhs + nb*32*GBS),  sm_u32(Bls + nb*32*GBS));
            cp_commit();
        }
        mma_ktile(sm_u32(Ahs + buf*128*GAS), sm_u32(Als + buf*128*GAS),
                  sm_u32(Bhs + buf*32*GBS),  sm_u32(Bls + buf*32*GBS),
                  mrow, ncol, lane, acc);
        buf ^= 1;
    }

#pragma unroll
    for (int im = 0; im < 4; im++) {
        int r0g = m0 + mrow + im*16 + (lane >> 2);
#pragma unroll
        for (int f = 0; f < 4; f++) {
            int gcol = n0 + ncol + f*8 + ((lane & 3) << 1);
            float* d = acc[im][f];
#pragma unroll
            for (int hfi = 0; hfi < 2; hfi++) {
                int rr = r0g + hfi*8;
                float x0 = d[hfi*2]     + bias[gcol];
                float x1 = d[hfi*2 + 1] + bias[gcol + 1];
                if (sel == 0) {
                    const float* mk = mask + (rr / L.nseq) * 64;
                    x0 = x0*0.125f + mk[gcol & 63];
                    x1 = x1*0.125f + mk[(gcol + 1) & 63];
                }
                size_t o = (size_t)(L.orow + rr) * HD + gcol;
                float h0,l0,h1,l1;
                fsplit(x0,h0,l0); fsplit(x1,h1,l1);
                *(uint32_t*)(Ch + o) = bpack(h0,h1);
                *(uint32_t*)(Cl + o) = bpack(l0,l1);
            }
        }
    }
}

#define VST ((128*GAS + 32*GBS) * 2)
#define OST VST
#define OUT_SMEM (3*OST)

// ---- output projection (round-13 plain): grid (6, 128) ----
__global__ __launch_bounds__(256, 2) void out_gemm(
    const hf* __restrict__ o, const hf* __restrict__ Wo,
    const float* __restrict__ bo, float* __restrict__ out)
{
    extern __shared__ char dsc[];
    const int tid = threadIdx.x, lane = tid & 31, warp = tid >> 5;
    const int n0 = blockIdx.x * 128, m0 = blockIdx.y * 128;
    const int mrow = (warp >> 2) * 64, ncol = (warp & 3) * 32;

    const bool lower = (m0 & 2047) < 1024;
    const int nkt = lower ? 24 : 12;
    const long o1r0 = (long)M0 + (m0 >> 11) * 1024 + (m0 & 2047);
    const uint32_t sb = sm_u32(dsc);

    float acc[4][4][4];
#pragma unroll
    for (int i = 0; i < 4; i++)
#pragma unroll
        for (int j = 0; j < 4; j++)
#pragma unroll
            for (int k = 0; k < 4; k++) acc[i][j][k] = 0.f;

    auto issue = [&](int t) {
        const hf* a; int kc, wr;
        if (t < 12) { a = o + (size_t)m0*HD;   kc = t*32;      wr = t*32; }
        else        { a = o + (size_t)o1r0*HD; kc = (t-12)*32; wr = 768 + (t-12)*32; }
        uint32_t s = sb + (t % 3) * OST;
        const hf* ap = a + kc;
        const hf* w = Wo + (size_t)wr*768 + n0;
        const int arow = tid >> 1, ak = (tid & 1) << 4;
        const size_t ao = (size_t)arow * HD + ak;
        const uint32_t ad = (uint32_t)(arow * GAS + ak) * 2;
        cpa16(s + ad, ap + ao);  cpa16(s + ad + 16, ap + ao + 8);
        const int brow = tid >> 3, bc = (tid & 7) << 4;
        const size_t bo_ = (size_t)brow * 768 + bc;
        const uint32_t bd = (uint32_t)(brow * GBS + bc) * 2 + 128*GAS*2;
        cpa16(s + bd, w + bo_);  cpa16(s + bd + 16, w + bo_ + 8);
        cp_commit();
    };

    issue(0); issue(1);
    for (int t = 0; t < nkt; t++) {
        if (t + 1 < nkt) cp_wait1(); else cp_wait0();
        __syncthreads();
        if (t + 2 < nkt) issue(t + 2);
        uint32_t s = sb + (t % 3) * OST;
        mma_ktile_h1(s, s + 128*GAS*2, mrow, ncol, lane, acc);
        __syncthreads();
    }

#pragma unroll
    for (int im = 0; im < 4; im++) {
        int r0g = m0 + mrow + im*16 + (lane >> 2);
#pragma unroll
        for (int f = 0; f < 4; f++) {
            int gcol = n0 + ncol + f*8 + ((lane & 3) << 1);
            float* d = acc[im][f];
#pragma unroll
            for (int hfi = 0; hfi < 2; hfi++) {
                int rr = r0g + hfi*8;
                out[(size_t)rr*768 + gcol]     = d[hfi*2]     + bo[gcol];
                out[(size_t)rr*768 + gcol + 1] = d[hfi*2 + 1] + bo[gcol + 1];
            }
        }
    }
}

// ---- merged flash attention (round-13 plain): grid (24, 48); x<16 level0 ----
#define AS 72
#define KLB (64*AS*2)
#define SBUF (3*KLB)
#define ATTN_SMEM (3*SBUF)

__global__ __launch_bounds__(256, 2) void attn_mma(
    const bf* __restrict__ qh, const bf* __restrict__ ql,
    const bf* __restrict__ kh, const bf* __restrict__ kl,
    const hf* __restrict__ v, hf* __restrict__ om)
{
    extern __shared__ char smc[];
    bf* smem = (bf*)smc;
    const int tid = threadIdx.x, lane = tid & 31, warp = tid >> 5;
    const int lvl = blockIdx.x >= 16;
    const int qt = lvl ? blockIdx.x - 16 : blockIdx.x;
    const int Nq = lvl ? N1 : N0;
    const size_t lbase = lvl ? (size_t)M0 * HD : 0;
    const int b = blockIdx.y / NH, h = blockIdx.y % NH;
    const int q0 = qt * 128;
    const size_t gb = lbase + (size_t)b*Nq*HD + (size_t)h*64;
    const int mrow = warp * 16;

    {
        const bf* Qh = qh + gb + (size_t)q0*HD;
        const bf* Ql = ql + gb + (size_t)q0*HD;
#pragma unroll
        for (int it = 0; it < 4; it++) {
            int i = tid + it*256, r = i >> 3, u = (i & 7)*8;
            *(uint4*)&smem[r*AS + u]          = *(const uint4*)&Qh[(size_t)r*HD + u];
            *(uint4*)&smem[128*AS + r*AS + u] = *(const uint4*)&Ql[(size_t)r*HD + u];
        }
    }
    __syncthreads();
    uint32_t qfh[4][4], qfl[4][4];
    {
        const uint32_t bh_ = sm_u32(smem), bl_ = sm_u32(smem) + 128*AS*2;
        int row = mrow + (lane & 15);
#pragma unroll
        for (int kk = 0; kk < 4; kk++) {
            uint32_t off = (uint32_t)(row*AS + kk*16 + ((lane >> 4) << 3))*2;
            ldsm4(qfh[kk], bh_ + off);
            ldsm4(qfl[kk], bl_ + off);
        }
    }
    __syncthreads();

    const uint32_t base0 = sm_u32(smc);
    auto kvload = [&](int s) {
        int kv = s * 64;
        const bf* Kh = kh + gb + (size_t)kv*HD;
        const bf* Kl = kl + gb + (size_t)kv*HD;
        const hf* V  = v  + gb + (size_t)kv*HD;
        uint32_t d = base0 + (s % 3) * SBUF;
#pragma unroll
        for (int it = 0; it < 2; it++) {
            int i = tid + it*256, r = i >> 3, u = (i & 7)*8;
            size_t go = (size_t)r*HD + u;
            uint32_t so = (uint32_t)(r*AS + u)*2;
            cpa16(d + so,         Kh + go);
            cpa16(d + KLB + so,   Kl + go);
            cpa16(d + 2*KLB + so, V  + go);
        }
        cp_commit();
    };

    float o[8][4];
#pragma unroll
    for (int f = 0; f < 8; f++)
#pragma unroll
        for (int k = 0; k < 4; k++) o[f][k] = 0.f;
    float mr0 = -1e30f, mr1 = -1e30f, lr0 = 0.f, lr1 = 0.f;

    const int S = Nq / 64;
    kvload(0); kvload(1);
    for (int t = 0; t < S; t++) {
        if (t + 1 < S) cp_wait1(); else cp_wait0();
        __syncthreads();
        if (t + 2 < S) kvload(t + 2);

        const uint32_t bb = base0 + (t % 3) * SBUF;
        const uint32_t kBH = bb, kBL = bb + KLB, vB = bb + 2*KLB;

        float s[8][4];
#pragma unroll
        for (int f = 0; f < 8; f++)
#pragma unroll
            for (int k = 0; k < 4; k++) s[f][k] = 0.f;
#pragma unroll
        for (int kk = 0; kk < 4; kk++) {
#pragma unroll
            for (int nf = 0; nf < 4; nf++) {
                uint32_t ad = (uint32_t)((nf*16 + (lane & 15))*AS + kk*16 +
                                         ((lane >> 4) << 3))*2;
                uint32_t kb[4], kl4[4];
                ldsm4(kb, kBH + ad); ldsm4(kl4, kBL + ad);
                mma_bf(s[nf*2],   qfh[kk], kb[0],  kb[2]);
                mma_bf(s[nf*2],   qfh[kk], kl4[0], kl4[2]);
                mma_bf(s[nf*2],   qfl[kk], kb[0],  kb[2]);
                mma_bf(s[nf*2+1], qfh[kk], kb[1],  kb[3]);
                mma_bf(s[nf*2+1], qfh[kk], kl4[1], kl4[3]);
                mma_bf(s[nf*2+1], qfl[kk], kb[1],  kb[3]);
            }
        }

        float mx0 = -1e30f, mx1 = -1e30f;
#pragma unroll
        for (int f = 0; f < 8; f++) {
            mx0 = fmaxf(mx0, fmaxf(s[f][0], s[f][1]));
            mx1 = fmaxf(mx1, fmaxf(s[f][2], s[f][3]));
        }
        mx0 = fmaxf(mx0, __shfl_xor_sync(~0u, mx0, 1));
        mx0 = fmaxf(mx0, __shfl_xor_sync(~0u, mx0, 2));
        mx1 = fmaxf(mx1, __shfl_xor_sync(~0u, mx1, 1));
        mx1 = fmaxf(mx1, __shfl_xor_sync(~0u, mx1, 2));
        float mn0 = fmaxf(mr0, mx0), mn1 = fmaxf(mr1, mx1);
        float c0 = __expf(mr0 - mn0), c1 = __expf(mr1 - mn1);
        float rs0 = 0.f, rs1 = 0.f;
#pragma unroll
        for (int f = 0; f < 8; f++) {
            s[f][0] = __expf(s[f][0] - mn0); s[f][1] = __expf(s[f][1] - mn0);
            s[f][2] = __expf(s[f][2] - mn1); s[f][3] = __expf(s[f][3] - mn1);
            rs0 += s[f][0] + s[f][1]; rs1 += s[f][2] + s[f][3];
        }
        rs0 += __shfl_xor_sync(~0u, rs0, 1); rs0 += __shfl_xor_sync(~0u, rs0, 2);
        rs1 += __shfl_xor_sync(~0u, rs1, 1); rs1 += __shfl_xor_sync(~0u, rs1, 2);
        lr0 = lr0*c0 + rs0; lr1 = lr1*c1 + rs1;
        mr0 = mn0; mr1 = mn1;
#pragma unroll
        for (int f = 0; f < 8; f++) {
            o[f][0] *= c0; o[f][1] *= c0; o[f][2] *= c1; o[f][3] *= c1;
        }

#pragma unroll
        for (int kk2 = 0; kk2 < 4; kk2++) {
            uint32_t pa[4];
            {
                int f0 = kk2*2;
                pa[0] = hpack(s[f0][0],   s[f0][1]);
                pa[1] = hpack(s[f0][2],   s[f0][3]);
                pa[2] = hpack(s[f0+1][0], s[f0+1][1]);
                pa[3] = hpack(s[f0+1][2], s[f0+1][3]);
            }
#pragma unroll
            for (int nf = 0; nf < 4; nf++) {
                uint32_t ad = (uint32_t)((kk2*16 + (lane & 15))*AS + nf*16 +
                                         ((lane >> 4) << 3))*2;
                uint32_t vb[4];
                ldsm4t(vb, vB + ad);
                mma_hf(o[nf*2],   pa, vb[0], vb[1]);
                mma_hf(o[nf*2+1], pa, vb[2], vb[3]);
            }
        }
    }

    float i0 = 1.f/lr0, i1 = 1.f/lr1;
    int rg = q0 + mrow + (lane >> 2);
#pragma unroll
    for (int f = 0; f < 8; f++) {
        int cc = f*8 + ((lane & 3) << 1);
        *(uint32_t*)(om + gb + (size_t)rg*HD + cc)     = hpack(o[f][0]*i0, o[f][1]*i0);
        *(uint32_t*)(om + gb + (size_t)(rg+8)*HD + cc) = hpack(o[f][2]*i1, o[f][3]*i1);
    }
}

__global__ void mask_kernel(float* __restrict__ out) {
    int i = blockIdx.x*blockDim.x + threadIdx.x;
    if (i < 2*N0) {
        int lvl = i >> 11, n = i & (N0 - 1);
        out[i] = (lvl == 0 || n < N1) ? 1.f : 0.f;
    }
}

extern "C" void kernel_launch(void* const* d_in, const int* in_sizes, int n_in,
                              void* d_out, int out_size)
{
    (void)in_sizes; (void)n_in; (void)out_size;
    const float* inp0 = (const float*)d_in[0];
    const float* inp1 = (const float*)d_in[1];
    const float* amask = (const float*)d_in[2];
    const float *Wq0 = (const float*)d_in[3],  *bq0 = (const float*)d_in[4];
    const float *Wk0 = (const float*)d_in[5],  *bk0 = (const float*)d_in[6];
    const float *Wv0 = (const float*)d_in[7],  *bv0 = (const float*)d_in[8];
    const float *Wq1 = (const float*)d_in[9],  *bq1 = (const float*)d_in[10];
    const float *Wk1 = (const float*)d_in[11], *bk1 = (const float*)d_in[12];
    const float *Wv1 = (const float*)d_in[13], *bv1 = (const float*)d_in[14];
    const float *Wo  = (const float*)d_in[15], *bo  = (const float*)d_in[16];
    float* out = (float*)d_out;

    bf *ih0,*il0,*ih1,*il1,*wh0,*wl0,*wh1,*wl1,*qh,*ql,*kh,*kl;
    hf *if0,*if1,*wv0f,*wv1f,*wo,*v,*o;
    cudaGetSymbolAddress((void**)&ih0,g_ih0); cudaGetSymbolAddress((void**)&il0,g_il0);
    cudaGetSymbolAddress((void**)&ih1,g_ih1); cudaGetSymbolAddress((void**)&il1,g_il1);
    cudaGetSymbolAddress((void**)&if0,g_if0); cudaGetSymbolAddress((void**)&if1,g_if1);
    cudaGetSymbolAddress((void**)&wh0,g_wh0); cudaGetSymbolAddress((void**)&wl0,g_wl0);
    cudaGetSymbolAddress((void**)&wh1,g_wh1); cudaGetSymbolAddress((void**)&wl1,g_wl1);
    cudaGetSymbolAddress((void**)&wv0f,g_wv0f); cudaGetSymbolAddress((void**)&wv1f,g_wv1f);
    cudaGetSymbolAddress((void**)&wo,g_wo);
    cudaGetSymbolAddress((void**)&qh,g_qh); cudaGetSymbolAddress((void**)&ql,g_ql);
    cudaGetSymbolAddress((void**)&kh,g_kh); cudaGetSymbolAddress((void**)&kl,g_kl);
    cudaGetSymbolAddress((void**)&v,g_v);   cudaGetSymbolAddress((void**)&o,g_o);

    cudaFuncSetAttribute(qkv_gemm, cudaFuncAttributeMaxDynamicSharedMemorySize, GEMM_SMEM);
    cudaFuncSetAttribute(out_gemm, cudaFuncAttributeMaxDynamicSharedMemorySize, OUT_SMEM);
    cudaFuncSetAttribute(attn_mma, cudaFuncAttributeMaxDynamicSharedMemorySize, ATTN_SMEM);

    // prep
    S3Jobs j3 = {{ {inp0, ih0, il0, if0}, {inp1, ih1, il1, if1} }};
    split3<<<dim3(2048,1,2), 256>>>(j3, M0*768);
    SJobs j0 = {{ {Wq0, wh0, wl0}, {Wk0, wh0 + 768*768, wl0 + 768*768} }};
    splitk<<<dim3(256,1,2), 256>>>(j0, 768*768);
    SJobs j1 = {{ {Wq1, wh1, wl1}, {Wk1, wh1 + 1536*768, wl1 + 1536*768} }};
    splitk<<<dim3(512,1,2), 256>>>(j1, 1536*768);
    CJobs jc = {{ {Wo, wo, 1536*768}, {Wv0, wv0f, 768*768}, {Wv1, wv1f, 1536*768} }};
    cvt3<<<dim3(512,1,3), 256>>>(jc);

    dim3 blk(256);
    QLv ql0 = {ih0, il0, wh0, wl0, if0, wv0f, bq0, bk0, bv0, 768, N0, 0, 0};
    QLv ql1 = {ih1, il1, wh1, wl1, if1, wv1f, bq1 + 384, bk1 + 384, bv1 + 384,
               1536, N1, 384, M0};
    qkv_gemm<<<dim3(9, 192), blk, GEMM_SMEM>>>(ql0, ql1, qh, ql, kh, kl, v, amask);

    attn_mma<<<dim3(24, 48), blk, ATTN_SMEM>>>(qh, ql, kh, kl, v, o);

    out_gemm<<<dim3(6, 128), blk, OUT_SMEM>>>(o, wo, bo, out);
    mask_kernel<<<16, 256>>>(out + OUT_ELEMS);
}

// round 17
// speedup vs baseline: 1.0761x; 1.0335x over previous
#include <cuda_runtime.h>
#include <cuda_fp16.h>
#include <stdint.h>
typedef __half hf;

#define B 8
#define N0 2048
#define N1 1024
#define HD 384
#define NH 6
#define M0 (B*N0)
#define M1 (B*N1)
#define MT (M0+M1)
#define OUT_ELEMS ((size_t)B*N0*768)

// all h/l pairs are fp16 exact splits: h = fp16(x), l = fp16(x - h)
__device__ __align__(128) hf g_ih0[M0*768],  g_il0[M0*768];
__device__ __align__(128) hf g_ih1[M1*1536], g_il1[M1*1536];
__device__ __align__(128) hf g_wh0[2][768*768],  g_wl0[2][768*768];
__device__ __align__(128) hf g_wh1[2][1536*768], g_wl1[2][1536*768];
__device__ __align__(128) hf g_wv0f[768*768], g_wv1f[1536*768], g_wo[1536*768];
__device__ __align__(128) hf g_qh[MT*HD], g_ql[MT*HD], g_kh[MT*HD], g_kl[MT*HD];
__device__ __align__(128) hf g_v[MT*HD];
__device__ __align__(128) hf g_o[MT*HD];

__device__ __forceinline__ uint32_t sm_u32(const void* p) {
    return (uint32_t)__cvta_generic_to_shared(p);
}
__device__ __forceinline__ void ldsm4(uint32_t r[4], uint32_t a) {
    asm volatile("ldmatrix.sync.aligned.m8n8.x4.shared.b16 {%0,%1,%2,%3}, [%4];"
        : "=r"(r[0]), "=r"(r[1]), "=r"(r[2]), "=r"(r[3]) : "r"(a));
}
__device__ __forceinline__ void ldsm4t(uint32_t r[4], uint32_t a) {
    asm volatile("ldmatrix.sync.aligned.m8n8.x4.trans.shared.b16 {%0,%1,%2,%3}, [%4];"
        : "=r"(r[0]), "=r"(r[1]), "=r"(r[2]), "=r"(r[3]) : "r"(a));
}
__device__ __forceinline__ void mma_hf(float d[4], const uint32_t a[4],
                                       uint32_t b0, uint32_t b1) {
    asm volatile("mma.sync.aligned.m16n8k16.row.col.f32.f16.f16.f32 "
        "{%0,%1,%2,%3}, {%4,%5,%6,%7}, {%8,%9}, {%0,%1,%2,%3};"
        : "+f"(d[0]), "+f"(d[1]), "+f"(d[2]), "+f"(d[3])
        : "r"(a[0]), "r"(a[1]), "r"(a[2]), "r"(a[3]), "r"(b0), "r"(b1));
}
__device__ __forceinline__ uint32_t hpack(float lo, float hi) {
    __half2 t = __floats2half2_rn(lo, hi);
    return *reinterpret_cast<uint32_t*>(&t);
}
__device__ __forceinline__ void hsplit(float x, float& h, float& l) {
    hf b = __float2half_rn(x);
    h = __half2float(b);
    l = x - h;
}
__device__ __forceinline__ void cpa16(uint32_t d, const void* s) {
    asm volatile("cp.async.cg.shared.global [%0], [%1], 16;" :: "r"(d), "l"(s));
}
__device__ __forceinline__ void cp_commit() { asm volatile("cp.async.commit_group;"); }
__device__ __forceinline__ void cp_wait0()  { asm volatile("cp.async.wait_group 0;"); }
__device__ __forceinline__ void cp_wait1()  { asm volatile("cp.async.wait_group 1;"); }

// ---- prep kernels (fp16 h/l exact split) ----
struct SJob  { const float* s; hf* h; hf* l; };
struct SJobs { SJob j[2]; };
__global__ void splitk(SJobs js, int n) {
    SJob J = js.j[blockIdx.z];
    for (int i = (blockIdx.x*256 + threadIdx.x)*4; i < n; i += gridDim.x*256*4) {
        float4 v = *(const float4*)(J.s + i);
        float h0,l0,h1,l1,h2,l2,h3,l3;
        hsplit(v.x,h0,l0); hsplit(v.y,h1,l1); hsplit(v.z,h2,l2); hsplit(v.w,h3,l3);
        *(uint2*)(J.h + i) = make_uint2(hpack(h0,h1), hpack(h2,h3));
        *(uint2*)(J.l + i) = make_uint2(hpack(l0,l1), hpack(l2,l3));
    }
}
struct CJob  { const float* s; hf* d; int n; };
struct CJobs { CJob j[3]; };
__global__ void cvt3(CJobs js) {
    CJob J = js.j[blockIdx.z];
    for (int i = (blockIdx.x*256 + threadIdx.x)*4; i < J.n; i += gridDim.x*256*4) {
        float4 v = *(const float4*)(J.s + i);
        *(uint2*)(J.d + i) = make_uint2(hpack(v.x, v.y), hpack(v.z, v.w));
    }
}

// ---- tile constants ----
#define GAS 40
#define GBS 136
#define GEMM_SMEM ((2*128*GAS + 2*32*GBS) * 2 * 2)   // 75776 B -> 2 CTAs/SM

// fp16 3-term ktile (A = Ah+Al exact, B = Bh+Bl exact; drop Al*Bl)
__device__ __forceinline__ void mma_ktile(
    uint32_t aBH, uint32_t aBL, uint32_t bBH, uint32_t bBL,
    int mrow, int ncol, int lane, float acc[4][4][4])
{
#pragma unroll
    for (int kk = 0; kk < 32; kk += 16) {
        uint32_t ah[4][4], al[4][4];
#pragma unroll
        for (int im = 0; im < 4; im++) {
            uint32_t ad = (uint32_t)((mrow + im*16 + (lane & 15)) * GAS +
                                     kk + ((lane >> 4) << 3)) * 2;
            ldsm4(ah[im], aBH + ad);
            ldsm4(al[im], aBL + ad);
        }
#pragma unroll
        for (int nf = 0; nf < 2; nf++) {
            uint32_t bd = (uint32_t)((kk + (lane & 15)) * GBS + ncol +
                                     nf*16 + ((lane >> 4) << 3)) * 2;
            uint32_t bh4[4], bl4[4];
            ldsm4t(bh4, bBH + bd);
            ldsm4t(bl4, bBL + bd);
#pragma unroll
            for (int im = 0; im < 4; im++) {
#pragma unroll
                for (int j = 0; j < 2; j++) {
                    float* d = acc[im][nf*2 + j];
                    mma_hf(d, ah[im], bh4[2*j], bh4[2*j+1]);
                    mma_hf(d, ah[im], bl4[2*j], bl4[2*j+1]);
                    mma_hf(d, al[im], bh4[2*j], bh4[2*j+1]);
                }
            }
        }
    }
}
// fp16 1-term ktile
__device__ __forceinline__ void mma_ktile_h1(
    uint32_t aB, uint32_t bB, int mrow, int ncol, int lane, float acc[4][4][4])
{
#pragma unroll
    for (int kk = 0; kk < 32; kk += 16) {
        uint32_t ah[4][4];
#pragma unroll
        for (int im = 0; im < 4; im++) {
            uint32_t ad = (uint32_t)((mrow + im*16 + (lane & 15)) * GAS +
                                     kk + ((lane >> 4) << 3)) * 2;
            ldsm4(ah[im], aB + ad);
        }
#pragma unroll
        for (int nf = 0; nf < 2; nf++) {
            uint32_t bd = (uint32_t)((kk + (lane & 15)) * GBS + ncol +
                                     nf*16 + ((lane >> 4) << 3)) * 2;
            uint32_t b4[4];
            ldsm4t(b4, bB + bd);
#pragma unroll
            for (int im = 0; im < 4; im++) {
#pragma unroll
                for (int j = 0; j < 2; j++)
                    mma_hf(acc[im][nf*2 + j], ah[im], b4[2*j], b4[2*j+1]);
            }
        }
    }
}
__device__ __forceinline__ void gemm_cpa(
    const hf* aH, const hf* aL, int lda,
    const hf* wH, const hf* wL, int ldw,
    int tid, uint32_t dAh, uint32_t dAl, uint32_t dBh, uint32_t dBl)
{
    const int arow = tid >> 1, ak = (tid & 1) << 4;
    const size_t ao = (size_t)arow * lda + ak;
    const uint32_t ad = (uint32_t)(arow * GAS + ak) * 2;
    cpa16(dAh + ad, aH + ao);  cpa16(dAh + ad + 16, aH + ao + 8);
    cpa16(dAl + ad, aL + ao);  cpa16(dAl + ad + 16, aL + ao + 8);
    const int brow = tid >> 3, bc = (tid & 7) << 4;
    const size_t bo = (size_t)brow * ldw + bc;
    const uint32_t bd = (uint32_t)(brow * GBS + bc) * 2;
    cpa16(dBh + bd, wH + bo);  cpa16(dBh + bd + 16, wH + bo + 8);
    cpa16(dBl + bd, wL + bo);  cpa16(dBl + bd + 16, wL + bo + 8);
}

// ---- merged Q/K projection (fp16 3-term): grid (6, 192); y<128 level0 ----
struct QLv {
    const hf *Ah, *Al, *Wh, *Wl;
    const float *bq, *bk;
    int K, nseq, wOff;
    long orow;
};
__global__ __launch_bounds__(256, 2) void qkv_gemm(
    QLv L0, QLv L1,
    hf* __restrict__ qh, hf* __restrict__ ql,
    hf* __restrict__ kh, hf* __restrict__ kl,
    const float* __restrict__ mask)
{
    extern __shared__ hf ds[];
    hf* Ahs = ds;
    hf* Als = Ahs + 2*128*GAS;
    hf* Bhs = Als + 2*128*GAS;
    hf* Bls = Bhs + 2*32*GBS;

    const int tid = threadIdx.x, lane = tid & 31, warp = tid >> 5;
    const QLv L = (blockIdx.y < 128) ? L0 : L1;
    const int myb = (blockIdx.y < 128) ? blockIdx.y : blockIdx.y - 128;
    const int sel = blockIdx.x / 3, n0 = (blockIdx.x % 3) * 128;
    const int m0 = myb * 128;
    const int K = L.K;
    const int mrow = (warp >> 2) * 64, ncol = (warp & 3) * 32;

    const hf* Wh = L.Wh + (size_t)sel * K * 768 + L.wOff + n0;
    const hf* Wl = L.Wl + (size_t)sel * K * 768 + L.wOff + n0;
    const float* bias = (sel == 0) ? L.bq : L.bk;
    hf* Ch = (sel == 0) ? qh : kh;
    hf* Cl = (sel == 0) ? ql : kl;
    const hf* aH = L.Ah + (size_t)m0 * K;
    const hf* aL = L.Al + (size_t)m0 * K;

    float acc[4][4][4];
#pragma unroll
    for (int i = 0; i < 4; i++)
#pragma unroll
        for (int j = 0; j < 4; j++)
#pragma unroll
            for (int k = 0; k < 4; k++) acc[i][j][k] = 0.f;

    gemm_cpa(aH, aL, K, Wh, Wl, 768, tid,
             sm_u32(Ahs), sm_u32(Als), sm_u32(Bhs), sm_u32(Bls));
    cp_commit();

    int buf = 0;
    for (int k0 = 0; k0 < K; k0 += 32) {
        cp_wait0();
        __syncthreads();
        if (k0 + 32 < K) {
            int nb = buf ^ 1;
            gemm_cpa(aH + k0 + 32, aL + k0 + 32, K,
                     Wh + (size_t)(k0 + 32)*768, Wl + (size_t)(k0 + 32)*768, 768, tid,
                     sm_u32(Ahs + nb*128*GAS), sm_u32(Als + nb*128*GAS),
                     sm_u32(Bhs + nb*32*GBS),  sm_u32(Bls + nb*32*GBS));
            cp_commit();
        }
        mma_ktile(sm_u32(Ahs + buf*128*GAS), sm_u32(Als + buf*128*GAS),
                  sm_u32(Bhs + buf*32*GBS),  sm_u32(Bls + buf*32*GBS),
                  mrow, ncol, lane, acc);
        buf ^= 1;
    }

#pragma unroll
    for (int im = 0; im < 4; im++) {
        int r0g = m0 + mrow + im*16 + (lane >> 2);
#pragma unroll
        for (int f = 0; f < 4; f++) {
            int gcol = n0 + ncol + f*8 + ((lane & 3) << 1);
            float* d = acc[im][f];
#pragma unroll
            for (int hfi = 0; hfi < 2; hfi++) {
                int rr = r0g + hfi*8;
                float x0 = d[hfi*2]     + bias[gcol];
                float x1 = d[hfi*2 + 1] + bias[gcol + 1];
                if (sel == 0) {
                    const float* mk = mask + (rr / L.nseq) * 64;
                    x0 = x0*0.125f + mk[gcol & 63];
                    x1 = x1*0.125f + mk[(gcol + 1) & 63];
                }
                size_t o = (size_t)(L.orow + rr) * HD + gcol;
                float h0,l0,h1,l1;
                hsplit(x0,h0,l0); hsplit(x1,h1,l1);
                *(uint32_t*)(Ch + o) = hpack(h0,h1);
                *(uint32_t*)(Cl + o) = hpack(l0,l1);
            }
        }
    }
}

#define VST ((128*GAS + 32*GBS) * 2)
#define V_SMEM (3*VST)

// ---- merged V projection (fp16 1-term, A = input h-plane): grid (3, 192) ----
struct VLv { const hf *A, *Wv; const float* bv; int K, wOff; long orow; };
__global__ __launch_bounds__(256, 2) void v_gemm(VLv L0, VLv L1, hf* __restrict__ v)
{
    extern __shared__ char dsc[];
    const int tid = threadIdx.x, lane = tid & 31, warp = tid >> 5;
    const VLv L = (blockIdx.y < 128) ? L0 : L1;
    const int myb = (blockIdx.y < 128) ? blockIdx.y : blockIdx.y - 128;
    const int n0 = blockIdx.x * 128, m0 = myb * 128;
    const int K = L.K;
    const int mrow = (warp >> 2) * 64, ncol = (warp & 3) * 32;
    const uint32_t sb = sm_u32(dsc);

    float acc[4][4][4];
#pragma unroll
    for (int i = 0; i < 4; i++)
#pragma unroll
        for (int j = 0; j < 4; j++)
#pragma unroll
            for (int k = 0; k < 4; k++) acc[i][j][k] = 0.f;

    auto issue = [&](int t) {
        uint32_t s = sb + (t % 3) * VST;
        const hf* a = L.A + (size_t)m0 * K + t*32;
        const hf* w = L.Wv + (size_t)(t*32) * 768 + L.wOff + n0;
        const int arow = tid >> 1, ak = (tid & 1) << 4;
        const size_t ao = (size_t)arow * K + ak;
        const uint32_t ad = (uint32_t)(arow * GAS + ak) * 2;
        cpa16(s + ad, a + ao);  cpa16(s + ad + 16, a + ao + 8);
        const int brow = tid >> 3, bc = (tid & 7) << 4;
        const size_t bo = (size_t)brow * 768 + bc;
        const uint32_t bd = (uint32_t)(brow * GBS + bc) * 2 + 128*GAS*2;
        cpa16(s + bd, w + bo);  cpa16(s + bd + 16, w + bo + 8);
        cp_commit();
    };

    const int nkt = K / 32;
    issue(0); issue(1);
    for (int t = 0; t < nkt; t++) {
        if (t + 1 < nkt) cp_wait1(); else cp_wait0();
        __syncthreads();
        if (t + 2 < nkt) issue(t + 2);
        uint32_t s = sb + (t % 3) * VST;
        mma_ktile_h1(s, s + 128*GAS*2, mrow, ncol, lane, acc);
        __syncthreads();
    }

#pragma unroll
    for (int im = 0; im < 4; im++) {
        int r0g = m0 + mrow + im*16 + (lane >> 2);
#pragma unroll
        for (int f = 0; f < 4; f++) {
            int gcol = n0 + ncol + f*8 + ((lane & 3) << 1);
            float* d = acc[im][f];
#pragma unroll
            for (int hfi = 0; hfi < 2; hfi++) {
                int rr = r0g + hfi*8;
                *(uint32_t*)(v + (size_t)(L.orow + rr)*HD + gcol) =
                    hpack(d[hfi*2] + L.bv[gcol], d[hfi*2 + 1] + L.bv[gcol + 1]);
            }
        }
    }
}

#define OST VST
#define OUT_SMEM (3*OST)

// ---- output projection (fp16 1-term A): grid (6, 128) ----
__global__ __launch_bounds__(256, 2) void out_gemm(
    const hf* __restrict__ o, const hf* __restrict__ Wo,
    const float* __restrict__ bo, float* __restrict__ out)
{
    extern __shared__ char dsc[];
    const int tid = threadIdx.x, lane = tid & 31, warp = tid >> 5;
    const int n0 = blockIdx.x * 128, m0 = blockIdx.y * 128;
    const int mrow = (warp >> 2) * 64, ncol = (warp & 3) * 32;

    const bool lower = (m0 & 2047) < 1024;
    const int nkt = lower ? 24 : 12;
    const long o1r0 = (long)M0 + (m0 >> 11) * 1024 + (m0 & 2047);
    const uint32_t sb = sm_u32(dsc);

    float acc[4][4][4];
#pragma unroll
    for (int i = 0; i < 4; i++)
#pragma unroll
        for (int j = 0; j < 4; j++)
#pragma unroll
            for (int k = 0; k < 4; k++) acc[i][j][k] = 0.f;

    auto issue = [&](int t) {
        const hf* a; int kc, wr;
        if (t < 12) { a = o + (size_t)m0*HD;   kc = t*32;      wr = t*32; }
        else        { a = o + (size_t)o1r0*HD; kc = (t-12)*32; wr = 768 + (t-12)*32; }
        uint32_t s = sb + (t % 3) * OST;
        const hf* ap = a + kc;
        const hf* w = Wo + (size_t)wr*768 + n0;
        const int arow = tid >> 1, ak = (tid & 1) << 4;
        const size_t ao = (size_t)arow * HD + ak;
        const uint32_t ad = (uint32_t)(arow * GAS + ak) * 2;
        cpa16(s + ad, ap + ao);  cpa16(s + ad + 16, ap + ao + 8);
        const int brow = tid >> 3, bc = (tid & 7) << 4;
        const size_t bo_ = (size_t)brow * 768 + bc;
        const uint32_t bd = (uint32_t)(brow * GBS + bc) * 2 + 128*GAS*2;
        cpa16(s + bd, w + bo_);  cpa16(s + bd + 16, w + bo_ + 8);
        cp_commit();
    };

    issue(0); issue(1);
    for (int t = 0; t < nkt; t++) {
        if (t + 1 < nkt) cp_wait1(); else cp_wait0();
        __syncthreads();
        if (t + 2 < nkt) issue(t + 2);
        uint32_t s = sb + (t % 3) * OST;
        mma_ktile_h1(s, s + 128*GAS*2, mrow, ncol, lane, acc);
        __syncthreads();
    }

#pragma unroll
    for (int im = 0; im < 4; im++) {
        int r0g = m0 + mrow + im*16 + (lane >> 2);
#pragma unroll
        for (int f = 0; f < 4; f++) {
            int gcol = n0 + ncol + f*8 + ((lane & 3) << 1);
            float* d = acc[im][f];
#pragma unroll
            for (int hfi = 0; hfi < 2; hfi++) {
                int rr = r0g + hfi*8;
                out[(size_t)rr*768 + gcol]     = d[hfi*2]     + bo[gcol];
                out[(size_t)rr*768 + gcol + 1] = d[hfi*2 + 1] + bo[gcol + 1];
            }
        }
    }
}

// ---- merged flash attention: grid (24, 48); x<16 level0 ----
#define AS 72
#define KLB (64*AS*2)
#define SBUF (3*KLB)
#define ATTN_SMEM (3*SBUF)

__global__ __launch_bounds__(256, 2) void attn_mma(
    const hf* __restrict__ qh, const hf* __restrict__ ql,
    const hf* __restrict__ kh, const hf* __restrict__ kl,
    const hf* __restrict__ v, hf* __restrict__ om)
{
    extern __shared__ char smc[];
    hf* smem = (hf*)smc;
    const int tid = threadIdx.x, lane = tid & 31, warp = tid >> 5;
    const int lvl = blockIdx.x >= 16;
    const int qt = lvl ? blockIdx.x - 16 : blockIdx.x;
    const int Nq = lvl ? N1 : N0;
    const size_t lbase = lvl ? (size_t)M0 * HD : 0;
    const int b = blockIdx.y / NH, h = blockIdx.y % NH;
    const int q0 = qt * 128;
    const size_t gb = lbase + (size_t)b*Nq*HD + (size_t)h*64;
    const int mrow = warp * 16;

    {
        const hf* Qh = qh + gb + (size_t)q0*HD;
        const hf* Ql = ql + gb + (size_t)q0*HD;
#pragma unroll
        for (int it = 0; it < 4; it++) {
            int i = tid + it*256, r = i >> 3, u = (i & 7)*8;
            *(uint4*)&smem[r*AS + u]          = *(const uint4*)&Qh[(size_t)r*HD + u];
            *(uint4*)&smem[128*AS + r*AS + u] = *(const uint4*)&Ql[(size_t)r*HD + u];
        }
    }
    __syncthreads();
    uint32_t qfh[4][4], qfl[4][4];
    {
        const uint32_t bh_ = sm_u32(smem), bl_ = sm_u32(smem) + 128*AS*2;
        int row = mrow + (lane & 15);
#pragma unroll
        for (int kk = 0; kk < 4; kk++) {
            uint32_t off = (uint32_t)(row*AS + kk*16 + ((lane >> 4) << 3))*2;
            ldsm4(qfh[kk], bh_ + off);
            ldsm4(qfl[kk], bl_ + off);
        }
    }
    __syncthreads();

    const uint32_t base0 = sm_u32(smc);
    auto kvload = [&](int s) {
        int kv = s * 64;
        const hf* Kh = kh + gb + (size_t)kv*HD;
        const hf* Kl = kl + gb + (size_t)kv*HD;
        const hf* V  = v  + gb + (size_t)kv*HD;
        uint32_t d = base0 + (s % 3) * SBUF;
#pragma unroll
        for (int it = 0; it < 2; it++) {
            int i = tid + it*256, r = i >> 3, u = (i & 7)*8;
            size_t go = (size_t)r*HD + u;
            uint32_t so = (uint32_t)(r*AS + u)*2;
            cpa16(d + so,         Kh + go);
            cpa16(d + KLB + so,   Kl + go);
            cpa16(d + 2*KLB + so, V  + go);
        }
        cp_commit();
    };

    float o[8][4];
#pragma unroll
    for (int f = 0; f < 8; f++)
#pragma unroll
        for (int k = 0; k < 4; k++) o[f][k] = 0.f;
    float mr0 = -1e30f, mr1 = -1e30f, lr0 = 0.f, lr1 = 0.f;

    const int S = Nq / 64;
    kvload(0); kvload(1);
    for (int t = 0; t < S; t++) {
        if (t + 1 < S) cp_wait1(); else cp_wait0();
        __syncthreads();
        if (t + 2 < S) kvload(t + 2);

        const uint32_t bb = base0 + (t % 3) * SBUF;
        const uint32_t kBH = bb, kBL = bb + KLB, vB = bb + 2*KLB;

        float s[8][4];
#pragma unroll
        for (int f = 0; f < 8; f++)
#pragma unroll
            for (int k = 0; k < 4; k++) s[f][k] = 0.f;
#pragma unroll
        for (int kk = 0; kk < 4; kk++) {
#pragma unroll
            for (int nf = 0; nf < 4; nf++) {
                uint32_t ad = (uint32_t)((nf*16 + (lane & 15))*AS + kk*16 +
                                         ((lane >> 4) << 3))*2;
                uint32_t kb[4], kl4[4];
                ldsm4(kb, kBH + ad); ldsm4(kl4, kBL + ad);
                mma_hf(s[nf*2],   qfh[kk], kb[0],  kb[2]);
                mma_hf(s[nf*2],   qfh[kk], kl4[0], kl4[2]);
                mma_hf(s[nf*2],   qfl[kk], kb[0],  kb[2]);
                mma_hf(s[nf*2+1], qfh[kk], kb[1],  kb[3]);
                mma_hf(s[nf*2+1], qfh[kk], kl4[1], kl4[3]);
                mma_hf(s[nf*2+1], qfl[kk], kb[1],  kb[3]);
            }
        }

        float mx0 = -1e30f, mx1 = -1e30f;
#pragma unroll
        for (int f = 0; f < 8; f++) {
            mx0 = fmaxf(mx0, fmaxf(s[f][0], s[f][1]));
            mx1 = fmaxf(mx1, fmaxf(s[f][2], s[f][3]));
        }
        mx0 = fmaxf(mx0, __shfl_xor_sync(~0u, mx0, 1));
        mx0 = fmaxf(mx0, __shfl_xor_sync(~0u, mx0, 2));
        mx1 = fmaxf(mx1, __shfl_xor_sync(~0u, mx1, 1));
        mx1 = fmaxf(mx1, __shfl_xor_sync(~0u, mx1, 2));
        float mn0 = fmaxf(mr0, mx0), mn1 = fmaxf(mr1, mx1);
        float c0 = __expf(mr0 - mn0), c1 = __expf(mr1 - mn1);
        float rs0 = 0.f, rs1 = 0.f;
#pragma unroll
        for (int f = 0; f < 8; f++) {
            s[f][0] = __expf(s[f][0] - mn0); s[f][1] = __expf(s[f][1] - mn0);
            s[f][2] = __expf(s[f][2] - mn1); s[f][3] = __expf(s[f][3] - mn1);
            rs0 += s[f][0] + s[f][1]; rs1 += s[f][2] + s[f][3];
        }
        rs0 += __shfl_xor_sync(~0u, rs0, 1); rs0 += __shfl_xor_sync(~0u, rs0, 2);
        rs1 += __shfl_xor_sync(~0u, rs1, 1); rs1 += __shfl_xor_sync(~0u, rs1, 2);
        lr0 = lr0*c0 + rs0; lr1 = lr1*c1 + rs1;
        mr0 = mn0; mr1 = mn1;
#pragma unroll
        for (int f = 0; f < 8; f++) {
            o[f][0] *= c0; o[f][1] *= c0; o[f][2] *= c1; o[f][3] *= c1;
        }

#pragma unroll
        for (int kk2 = 0; kk2 < 4; kk2++) {
            uint32_t pa[4];
            {
                int f0 = kk2*2;
                pa[0] = hpack(s[f0][0],   s[f0][1]);
                pa[1] = hpack(s[f0][2],   s[f0][3]);
                pa[2] = hpack(s[f0+1][0], s[f0+1][1]);
                pa[3] = hpack(s[f0+1][2], s[f0+1][3]);
            }
#pragma unroll
            for (int nf = 0; nf < 4; nf++) {
                uint32_t ad = (uint32_t)((kk2*16 + (lane & 15))*AS + nf*16 +
                                         ((lane >> 4) << 3))*2;
                uint32_t vb[4];
                ldsm4t(vb, vB + ad);
                mma_hf(o[nf*2],   pa, vb[0], vb[1]);
                mma_hf(o[nf*2+1], pa, vb[2], vb[3]);
            }
        }
    }

    float i0 = 1.f/lr0, i1 = 1.f/lr1;
    int rg = q0 + mrow + (lane >> 2);
#pragma unroll
    for (int f = 0; f < 8; f++) {
        int cc = f*8 + ((lane & 3) << 1);
        *(uint32_t*)(om + gb + (size_t)rg*HD + cc)     = hpack(o[f][0]*i0, o[f][1]*i0);
        *(uint32_t*)(om + gb + (size_t)(rg+8)*HD + cc) = hpack(o[f][2]*i1, o[f][3]*i1);
    }
}

__global__ void mask_kernel(float* __restrict__ out) {
    int i = blockIdx.x*blockDim.x + threadIdx.x;
    if (i < 2*N0) {
        int lvl = i >> 11, n = i & (N0 - 1);
        out[i] = (lvl == 0 || n < N1) ? 1.f : 0.f;
    }
}

extern "C" void kernel_launch(void* const* d_in, const int* in_sizes, int n_in,
                              void* d_out, int out_size)
{
    (void)in_sizes; (void)n_in; (void)out_size;
    const float* inp0 = (const float*)d_in[0];
    const float* inp1 = (const float*)d_in[1];
    const float* amask = (const float*)d_in[2];
    const float *Wq0 = (const float*)d_in[3],  *bq0 = (const float*)d_in[4];
    const float *Wk0 = (const float*)d_in[5],  *bk0 = (const float*)d_in[6];
    const float *Wv0 = (const float*)d_in[7],  *bv0 = (const float*)d_in[8];
    const float *Wq1 = (const float*)d_in[9],  *bq1 = (const float*)d_in[10];
    const float *Wk1 = (const float*)d_in[11], *bk1 = (const float*)d_in[12];
    const float *Wv1 = (const float*)d_in[13], *bv1 = (const float*)d_in[14];
    const float *Wo  = (const float*)d_in[15], *bo  = (const float*)d_in[16];
    float* out = (float*)d_out;

    hf *ih0,*il0,*ih1,*il1,*wh0,*wl0,*wh1,*wl1,*qh,*ql,*kh,*kl;
    hf *wv0f,*wv1f,*wo,*v,*o;
    cudaGetSymbolAddress((void**)&ih0,g_ih0); cudaGetSymbolAddress((void**)&il0,g_il0);
    cudaGetSymbolAddress((void**)&ih1,g_ih1); cudaGetSymbolAddress((void**)&il1,g_il1);
    cudaGetSymbolAddress((void**)&wh0,g_wh0); cudaGetSymbolAddress((void**)&wl0,g_wl0);
    cudaGetSymbolAddress((void**)&wh1,g_wh1); cudaGetSymbolAddress((void**)&wl1,g_wl1);
    cudaGetSymbolAddress((void**)&wv0f,g_wv0f); cudaGetSymbolAddress((void**)&wv1f,g_wv1f);
    cudaGetSymbolAddress((void**)&wo,g_wo);
    cudaGetSymbolAddress((void**)&qh,g_qh); cudaGetSymbolAddress((void**)&ql,g_ql);
    cudaGetSymbolAddress((void**)&kh,g_kh); cudaGetSymbolAddress((void**)&kl,g_kl);
    cudaGetSymbolAddress((void**)&v,g_v);   cudaGetSymbolAddress((void**)&o,g_o);

    cudaFuncSetAttribute(qkv_gemm, cudaFuncAttributeMaxDynamicSharedMemorySize, GEMM_SMEM);
    cudaFuncSetAttribute(v_gemm,   cudaFuncAttributeMaxDynamicSharedMemorySize, V_SMEM);
    cudaFuncSetAttribute(out_gemm, cudaFuncAttributeMaxDynamicSharedMemorySize, OUT_SMEM);
    cudaFuncSetAttribute(attn_mma, cudaFuncAttributeMaxDynamicSharedMemorySize, ATTN_SMEM);

    // prep: inputs + q/k weights -> fp16 h/l; Wv/Wo -> fp16 single
    SJobs ji = {{ {inp0, ih0, il0}, {inp1, ih1, il1} }};
    splitk<<<dim3(2048,1,2), 256>>>(ji, M0*768);
    SJobs j0 = {{ {Wq0, wh0, wl0}, {Wk0, wh0 + 768*768, wl0 + 768*768} }};
    splitk<<<dim3(256,1,2), 256>>>(j0, 768*768);
    SJobs j1 = {{ {Wq1, wh1, wl1}, {Wk1, wh1 + 1536*768, wl1 + 1536*768} }};
    splitk<<<dim3(512,1,2), 256>>>(j1, 1536*768);
    CJobs jc = {{ {Wo, wo, 1536*768}, {Wv0, wv0f, 768*768}, {Wv1, wv1f, 1536*768} }};
    cvt3<<<dim3(512,1,3), 256>>>(jc);

    dim3 blk(256);
    QLv ql0 = {ih0, il0, wh0, wl0, bq0, bk0, 768, N0, 0, 0};
    QLv ql1 = {ih1, il1, wh1, wl1, bq1 + 384, bk1 + 384, 1536, N1, 384, M0};
    qkv_gemm<<<dim3(6, 192), blk, GEMM_SMEM>>>(ql0, ql1, qh, ql, kh, kl, amask);

    VLv vl0 = {ih0, wv0f, bv0, 768, 0, 0};
    VLv vl1 = {ih1, wv1f, bv1 + 384, 1536, 384, M0};
    v_gemm<<<dim3(3, 192), blk, V_SMEM>>>(vl0, vl1, v);

    attn_mma<<<dim3(24, 48), blk, ATTN_SMEM>>>(qh, ql, kh, kl, v, o);

    out_gemm<<<dim3(6, 128), blk, OUT_SMEM>>>(o, wo, bo, out);
    mask_kernel<<<16, 256>>>(out + OUT_ELEMS);
}